// round 1
// baseline (speedup 1.0000x reference)
#include <cuda_runtime.h>

// Problem constants
#define B_    4
#define N_    1024
#define EMB_  1024
#define H_    16
#define HD_   64
#define BQ_   (B_*H_*N_*HD_)   // 4194304 elements per qkv part

// Scratch (static device globals — no allocations allowed)
__device__ float g_qkv[3u * BQ_];        // [part][b][h][n][d], part: 0=K,1=Q,2=V
__device__ float g_att[B_ * N_ * EMB_];  // attention output, (B*N, H*hd) row-major

// ---------------------------------------------------------------------------
// GEMM1: qkv = x @ W_qkv + b_qkv ; scatter epilogue into g_qkv
// A: (4096, 1024) row-major, B: (1024, 3072) row-major
// 128x128 tile, BK=8, 256 threads, 8x8 per thread
// ---------------------------------------------------------------------------
__global__ __launch_bounds__(256) void gemm_qkv_kernel(
    const float* __restrict__ A, const float* __restrict__ Bm,
    const float* __restrict__ bias)
{
    const int K = 1024, Nc = 3072;
    __shared__ float As[8][128];
    __shared__ float Bs[8][128];

    const int tid = threadIdx.x;
    const int m0 = blockIdx.y * 128, n0 = blockIdx.x * 128;
    const int arow = tid >> 1, acol = (tid & 1) * 4;
    const int brow = tid >> 5, bcol = (tid & 31) * 4;
    const int ty = tid >> 4, tx = tid & 15;

    float acc[8][8];
    #pragma unroll
    for (int i = 0; i < 8; i++)
        #pragma unroll
        for (int j = 0; j < 8; j++) acc[i][j] = 0.f;

    for (int k0 = 0; k0 < K; k0 += 8) {
        float4 av = *(const float4*)(A + (size_t)(m0 + arow) * K + k0 + acol);
        As[acol + 0][arow] = av.x;
        As[acol + 1][arow] = av.y;
        As[acol + 2][arow] = av.z;
        As[acol + 3][arow] = av.w;
        *(float4*)(&Bs[brow][bcol]) =
            *(const float4*)(Bm + (size_t)(k0 + brow) * Nc + n0 + bcol);
        __syncthreads();

        #pragma unroll
        for (int kk = 0; kk < 8; kk++) {
            float ar[8], br[8];
            *(float4*)(ar)     = *(const float4*)(&As[kk][ty * 8]);
            *(float4*)(ar + 4) = *(const float4*)(&As[kk][ty * 8 + 4]);
            *(float4*)(br)     = *(const float4*)(&Bs[kk][tx * 8]);
            *(float4*)(br + 4) = *(const float4*)(&Bs[kk][tx * 8 + 4]);
            #pragma unroll
            for (int i = 0; i < 8; i++)
                #pragma unroll
                for (int j = 0; j < 8; j++)
                    acc[i][j] += ar[i] * br[j];
        }
        __syncthreads();
    }

    // Scatter epilogue: column c -> (part, h, d); row m -> (b, n)
    #pragma unroll
    for (int i = 0; i < 8; i++) {
        const int m = m0 + ty * 8 + i;
        const int b = m >> 10, n = m & 1023;
        #pragma unroll
        for (int j = 0; j < 8; j++) {
            const int c = n0 + tx * 8 + j;
            const float v = acc[i][j] + bias[c];
            const int part = c >> 10;
            const int col  = c & 1023;
            const int h = col >> 6, d = col & 63;
            g_qkv[(size_t)part * BQ_ +
                  ((size_t)((b << 4) + h) * 1024 + n) * 64 + d] = v;
        }
    }
}

// ---------------------------------------------------------------------------
// Flash attention, fp32. 1 thread = 1 query row. 128 queries / CTA.
// K/V tiles (32 keys x 64 d) staged in SMEM, broadcast-read (conflict-free).
// ---------------------------------------------------------------------------
__global__ __launch_bounds__(128) void attn_kernel()
{
    __shared__ float4 Ks[32 * 16];  // 32 keys x 64 floats
    __shared__ float4 Vs[32 * 16];

    const int tid = threadIdx.x;
    const int bh = blockIdx.y;                // b*16 + h
    const int q  = blockIdx.x * 128 + tid;    // query index within (b,h)

    const float* Kbase = g_qkv + (size_t)0 * BQ_ + (size_t)bh * N_ * HD_;
    const float* Qbase = g_qkv + (size_t)1 * BQ_ + (size_t)bh * N_ * HD_;
    const float* Vbase = g_qkv + (size_t)2 * BQ_ + (size_t)bh * N_ * HD_;

    float4 q4[16];
    {
        const float4* qp = (const float4*)(Qbase + (size_t)q * HD_);
        #pragma unroll
        for (int i = 0; i < 16; i++) q4[i] = qp[i];
    }

    float4 o4[16];
    #pragma unroll
    for (int i = 0; i < 16; i++) o4[i] = make_float4(0.f, 0.f, 0.f, 0.f);

    float mi = -1e30f, li = 0.f;
    // 1/sqrt(64) * log2(e): scores kept in log2 domain, use exp2f
    const float scale = 0.125f * 1.44269504088896f;

    for (int kt = 0; kt < N_; kt += 32) {
        const float4* ksrc = (const float4*)(Kbase + (size_t)kt * HD_);
        const float4* vsrc = (const float4*)(Vbase + (size_t)kt * HD_);
        #pragma unroll
        for (int i = 0; i < 4; i++) {
            Ks[tid + i * 128] = ksrc[tid + i * 128];
            Vs[tid + i * 128] = vsrc[tid + i * 128];
        }
        __syncthreads();

        float s[32];
        #pragma unroll
        for (int k = 0; k < 32; k++) {
            float acc = 0.f;
            #pragma unroll
            for (int d = 0; d < 16; d++) {
                const float4 kv = Ks[k * 16 + d];  // broadcast across all threads
                acc += q4[d].x * kv.x + q4[d].y * kv.y +
                       q4[d].z * kv.z + q4[d].w * kv.w;
            }
            s[k] = acc * scale;
        }

        float tm = s[0];
        #pragma unroll
        for (int k = 1; k < 32; k++) tm = fmaxf(tm, s[k]);
        const float mnew = fmaxf(mi, tm);
        const float alpha = exp2f(mi - mnew);
        li *= alpha;
        #pragma unroll
        for (int i = 0; i < 16; i++) {
            o4[i].x *= alpha; o4[i].y *= alpha;
            o4[i].z *= alpha; o4[i].w *= alpha;
        }

        #pragma unroll
        for (int k = 0; k < 32; k++) {
            const float p = exp2f(s[k] - mnew);
            li += p;
            #pragma unroll
            for (int d = 0; d < 16; d++) {
                const float4 vv = Vs[k * 16 + d];  // broadcast
                o4[d].x += p * vv.x; o4[d].y += p * vv.y;
                o4[d].z += p * vv.z; o4[d].w += p * vv.w;
            }
        }
        mi = mnew;
        __syncthreads();
    }

    const float inv = 1.f / li;
    const int b = bh >> 4, h = bh & 15;
    float4* outp = (float4*)(g_att + ((size_t)(b * N_ + q)) * EMB_ + h * HD_);
    #pragma unroll
    for (int d = 0; d < 16; d++)
        outp[d] = make_float4(o4[d].x * inv, o4[d].y * inv,
                              o4[d].z * inv, o4[d].w * inv);
}

// ---------------------------------------------------------------------------
// GEMM2: out = g_att @ W_out + b_out ; plain epilogue to d_out
// A: (4096, 1024), B: (1024, 1024)
// ---------------------------------------------------------------------------
__global__ __launch_bounds__(256) void gemm_out_kernel(
    const float* __restrict__ Bm, const float* __restrict__ bias,
    float* __restrict__ C)
{
    const int K = 1024, Nc = 1024;
    const float* A = g_att;
    __shared__ float As[8][128];
    __shared__ float Bs[8][128];

    const int tid = threadIdx.x;
    const int m0 = blockIdx.y * 128, n0 = blockIdx.x * 128;
    const int arow = tid >> 1, acol = (tid & 1) * 4;
    const int brow = tid >> 5, bcol = (tid & 31) * 4;
    const int ty = tid >> 4, tx = tid & 15;

    float acc[8][8];
    #pragma unroll
    for (int i = 0; i < 8; i++)
        #pragma unroll
        for (int j = 0; j < 8; j++) acc[i][j] = 0.f;

    for (int k0 = 0; k0 < K; k0 += 8) {
        float4 av = *(const float4*)(A + (size_t)(m0 + arow) * K + k0 + acol);
        As[acol + 0][arow] = av.x;
        As[acol + 1][arow] = av.y;
        As[acol + 2][arow] = av.z;
        As[acol + 3][arow] = av.w;
        *(float4*)(&Bs[brow][bcol]) =
            *(const float4*)(Bm + (size_t)(k0 + brow) * Nc + n0 + bcol);
        __syncthreads();

        #pragma unroll
        for (int kk = 0; kk < 8; kk++) {
            float ar[8], br[8];
            *(float4*)(ar)     = *(const float4*)(&As[kk][ty * 8]);
            *(float4*)(ar + 4) = *(const float4*)(&As[kk][ty * 8 + 4]);
            *(float4*)(br)     = *(const float4*)(&Bs[kk][tx * 8]);
            *(float4*)(br + 4) = *(const float4*)(&Bs[kk][tx * 8 + 4]);
            #pragma unroll
            for (int i = 0; i < 8; i++)
                #pragma unroll
                for (int j = 0; j < 8; j++)
                    acc[i][j] += ar[i] * br[j];
        }
        __syncthreads();
    }

    #pragma unroll
    for (int i = 0; i < 8; i++) {
        const int m = m0 + ty * 8 + i;
        float* crow = C + (size_t)m * Nc;
        #pragma unroll
        for (int j = 0; j < 8; j++) {
            const int c = n0 + tx * 8 + j;
            crow[c] = acc[i][j] + bias[c];
        }
    }
}

// ---------------------------------------------------------------------------
extern "C" void kernel_launch(void* const* d_in, const int* in_sizes, int n_in,
                              void* d_out, int out_size)
{
    const float* x    = (const float*)d_in[0];
    const float* Wqkv = (const float*)d_in[1];
    const float* bqkv = (const float*)d_in[2];
    const float* Wout = (const float*)d_in[3];
    const float* bout = (const float*)d_in[4];
    float* out = (float*)d_out;

    gemm_qkv_kernel<<<dim3(24, 32), 256>>>(x, Wqkv, bqkv);   // 3072/128 x 4096/128
    attn_kernel<<<dim3(8, 64), 128>>>();                     // 1024/128 x (B*H)
    gemm_out_kernel<<<dim3(8, 32), 256>>>(Wout, bout, out);  // 1024/128 x 4096/128
}

// round 3
// speedup vs baseline: 1.8543x; 1.8543x over previous
#include <cuda_runtime.h>
#include <cstdint>

// Problem constants
#define B_    4
#define N_    1024
#define EMB_  1024
#define H_    16
#define HD_   64
#define BQ_   (B_*H_*N_*HD_)   // 4194304 elements per qkv part

// Scratch (static device globals — no allocations allowed)
__device__ float g_xa [4096 * 1024];     // tf32-rounded x
__device__ float g_w1t[3072 * 1024];     // tf32(W_qkv^T)  (row n, K contiguous)
__device__ float g_w2t[1024 * 1024];     // tf32(W_out^T)
__device__ float g_qkv[3u * BQ_];        // [part][b][h][n][d], part: 0=K,1=Q,2=V
__device__ float g_att[4096 * 1024];     // attention out, tf32-rounded

// ---------------------------------------------------------------------------
// helpers
// ---------------------------------------------------------------------------
__device__ __forceinline__ float tf32_rna(float x) {
    float r;
    asm("cvt.rna.tf32.f32 %0, %1;" : "=f"(r) : "f"(x));
    return r;
}
__device__ __forceinline__ void cp_async16(uint32_t dst, const void* src) {
    asm volatile("cp.async.cg.shared.global [%0], [%1], 16;\n"
                 :: "r"(dst), "l"(src) : "memory");
}
__device__ __forceinline__ void cp_commit() {
    asm volatile("cp.async.commit_group;\n" ::: "memory");
}
__device__ __forceinline__ void cp_wait2() {
    asm volatile("cp.async.wait_group 2;\n" ::: "memory");
}
__device__ __forceinline__ uint32_t smem_u32(const void* p) {
    uint32_t a;
    asm("{ .reg .u64 t; cvta.to.shared.u64 t, %1; cvt.u32.u64 %0, t; }"
        : "=r"(a) : "l"(p));
    return a;
}
// m16n8k8 tf32 mma, acc fp32
__device__ __forceinline__ void mma_tf32(float* c, const uint32_t* a, const uint32_t* b) {
    asm volatile(
        "mma.sync.aligned.m16n8k8.row.col.f32.tf32.tf32.f32 "
        "{%0,%1,%2,%3}, {%4,%5,%6,%7}, {%8,%9}, {%0,%1,%2,%3};"
        : "+f"(c[0]), "+f"(c[1]), "+f"(c[2]), "+f"(c[3])
        : "r"(a[0]), "r"(a[1]), "r"(a[2]), "r"(a[3]),
          "r"(b[0]), "r"(b[1]));
}

// ---------------------------------------------------------------------------
// Prep kernels: tf32 round (+ transpose for weights)
// ---------------------------------------------------------------------------
__global__ void cvt_tf32_kernel(const float* __restrict__ in, float* __restrict__ out, int n4) {
    int i = blockIdx.x * blockDim.x + threadIdx.x;
    if (i >= n4) return;
    float4 v = ((const float4*)in)[i];
    v.x = tf32_rna(v.x); v.y = tf32_rna(v.y);
    v.z = tf32_rna(v.z); v.w = tf32_rna(v.w);
    ((float4*)out)[i] = v;
}

// W: (Kd x Nd) row-major -> Wt: (Nd x Kd), tf32-rounded
__global__ void transpose_cvt_kernel(const float* __restrict__ W, float* __restrict__ Wt,
                                     int Kd, int Nd) {
    __shared__ float ts[32][33];
    int bx = blockIdx.x * 32;   // n base
    int by = blockIdx.y * 32;   // k base
    #pragma unroll
    for (int i = 0; i < 4; i++)
        ts[threadIdx.y + i * 8][threadIdx.x] =
            W[(size_t)(by + threadIdx.y + i * 8) * Nd + bx + threadIdx.x];
    __syncthreads();
    #pragma unroll
    for (int i = 0; i < 4; i++)
        Wt[(size_t)(bx + threadIdx.y + i * 8) * Kd + by + threadIdx.x] =
            tf32_rna(ts[threadIdx.x][threadIdx.y + i * 8]);
}

// ---------------------------------------------------------------------------
// tf32 mma.sync GEMM: C(MxNc) = A(Mx1024) * Bt(Ncx1024)^T (+bias)
// 128x128 tile / CTA, 256 threads (8 warps, 2Mx4N), KC=32, 3-stage cp.async.
// SMEM row stride 36 floats => conflict-free fragment loads, 16B-aligned.
// MODE 0: scatter epilogue -> g_qkv ; MODE 1: plain -> outParam
// ---------------------------------------------------------------------------
#define KC 32
#define NITER 32
#define ROWSTRIDE 36
#define STAGE_FLOATS (2 * 128 * ROWSTRIDE)       // A tile + B tile = 9216
#define SMEM_BYTES (3 * STAGE_FLOATS * 4)        // 110592

__device__ __forceinline__ void issue_stage(const float* Aptr, const float* Bptr,
                                            uint32_t sbase, int slot, int kiter,
                                            int m0, int n0, int tid) {
    const uint32_t sA = sbase + slot * (STAGE_FLOATS * 4);
    const uint32_t sB = sA + 128 * ROWSTRIDE * 4;
    const int k0 = kiter * KC;
    #pragma unroll
    for (int j = 0; j < 4; j++) {
        int c = tid + j * 256;              // 0..1023
        int row = c >> 3, k4 = (c & 7) * 4; // k offset in floats
        cp_async16(sA + (row * ROWSTRIDE + k4) * 4,
                   Aptr + (size_t)(m0 + row) * 1024 + k0 + k4);
    }
    #pragma unroll
    for (int j = 0; j < 4; j++) {
        int c = tid + j * 256;
        int row = c >> 3, k4 = (c & 7) * 4;
        cp_async16(sB + (row * ROWSTRIDE + k4) * 4,
                   Bptr + (size_t)(n0 + row) * 1024 + k0 + k4);
    }
}

template<int MODE>
__global__ __launch_bounds__(256, 1) void tc_gemm_kernel(
    const float* __restrict__ bias, float* __restrict__ outParam)
{
    extern __shared__ float smem[];
    const uint32_t sbase = smem_u32(smem);
    const int tid = threadIdx.x;
    const int wid = tid >> 5, lid = tid & 31;
    const int grp = lid >> 2, tig = lid & 3;
    const int warpM = wid >> 2, warpN = wid & 3;   // 2 x 4
    const int m0 = blockIdx.y * 128, n0 = blockIdx.x * 128;

    const float* Aptr = (MODE == 0) ? g_xa  : g_att;
    const float* Bptr = (MODE == 0) ? g_w1t : g_w2t;

    float acc[4][4][4];
    #pragma unroll
    for (int mf = 0; mf < 4; mf++)
        #pragma unroll
        for (int nf = 0; nf < 4; nf++)
            #pragma unroll
            for (int r = 0; r < 4; r++) acc[mf][nf][r] = 0.f;

    #pragma unroll
    for (int s = 0; s < 3; s++) { issue_stage(Aptr, Bptr, sbase, s, s, m0, n0, tid); cp_commit(); }

    const int arow0 = warpM * 64 + grp;
    const int brow0 = warpN * 32 + grp;

    for (int i = 0; i < NITER; i++) {
        const int slot = i % 3;
        cp_wait2();
        __syncthreads();

        const float* As = smem + slot * STAGE_FLOATS;
        const float* Bs = As + 128 * ROWSTRIDE;

        #pragma unroll
        for (int ks = 0; ks < 4; ks++) {
            const int kc0 = ks * 8 + tig;
            uint32_t a[4][4], b[4][2];
            #pragma unroll
            for (int mf = 0; mf < 4; mf++) {
                const float* ap = As + (arow0 + mf * 16) * ROWSTRIDE + kc0;
                a[mf][0] = __float_as_uint(ap[0]);
                a[mf][1] = __float_as_uint(ap[8 * ROWSTRIDE]);
                a[mf][2] = __float_as_uint(ap[4]);
                a[mf][3] = __float_as_uint(ap[8 * ROWSTRIDE + 4]);
            }
            #pragma unroll
            for (int nf = 0; nf < 4; nf++) {
                const float* bp = Bs + (brow0 + nf * 8) * ROWSTRIDE + kc0;
                b[nf][0] = __float_as_uint(bp[0]);
                b[nf][1] = __float_as_uint(bp[4]);
            }
            #pragma unroll
            for (int mf = 0; mf < 4; mf++)
                #pragma unroll
                for (int nf = 0; nf < 4; nf++)
                    mma_tf32(acc[mf][nf], a[mf], b[nf]);
        }
        __syncthreads();
        if (i + 3 < NITER) issue_stage(Aptr, Bptr, sbase, slot, i + 3, m0, n0, tid);
        cp_commit();
    }

    // Epilogue
    #pragma unroll
    for (int mf = 0; mf < 4; mf++) {
        const int m = m0 + warpM * 64 + mf * 16 + grp;
        #pragma unroll
        for (int nf = 0; nf < 4; nf++) {
            const int c = n0 + warpN * 32 + nf * 8 + tig * 2;
            const float b0 = bias[c], b1 = bias[c + 1];
            float2 v0 = make_float2(acc[mf][nf][0] + b0, acc[mf][nf][1] + b1);
            float2 v1 = make_float2(acc[mf][nf][2] + b0, acc[mf][nf][3] + b1);
            if (MODE == 0) {
                const int bb = m >> 10, n = m & 1023;
                const int part = c >> 10, col = c & 1023;
                const int h = col >> 6, d = col & 63;
                float* base = g_qkv + (size_t)part * BQ_ +
                              ((size_t)((bb << 4) + h) * 1024) * 64 + d;
                *(float2*)(base + (size_t)n * 64)       = v0;
                *(float2*)(base + (size_t)(n + 8) * 64) = v1;
            } else {
                *(float2*)(outParam + (size_t)m * 1024 + c)       = v0;
                *(float2*)(outParam + (size_t)(m + 8) * 1024 + c) = v1;
            }
        }
    }
}

// ---------------------------------------------------------------------------
// Flash attention, fp32 SIMT. 1 thread = 1 query row. Writes tf32-rounded.
// ---------------------------------------------------------------------------
__global__ __launch_bounds__(128) void attn_kernel()
{
    __shared__ float4 Ks[32 * 16];
    __shared__ float4 Vs[32 * 16];

    const int tid = threadIdx.x;
    const int bh = blockIdx.y;
    const int q  = blockIdx.x * 128 + tid;

    const float* Kbase = g_qkv + (size_t)0 * BQ_ + (size_t)bh * N_ * HD_;
    const float* Qbase = g_qkv + (size_t)1 * BQ_ + (size_t)bh * N_ * HD_;
    const float* Vbase = g_qkv + (size_t)2 * BQ_ + (size_t)bh * N_ * HD_;

    float4 q4[16];
    {
        const float4* qp = (const float4*)(Qbase + (size_t)q * HD_);
        #pragma unroll
        for (int i = 0; i < 16; i++) q4[i] = qp[i];
    }

    float4 o4[16];
    #pragma unroll
    for (int i = 0; i < 16; i++) o4[i] = make_float4(0.f, 0.f, 0.f, 0.f);

    float mi = -1e30f, li = 0.f;
    const float scale = 0.125f * 1.44269504088896f;

    for (int kt = 0; kt < N_; kt += 32) {
        const float4* ksrc = (const float4*)(Kbase + (size_t)kt * HD_);
        const float4* vsrc = (const float4*)(Vbase + (size_t)kt * HD_);
        #pragma unroll
        for (int i = 0; i < 4; i++) {
            Ks[tid + i * 128] = ksrc[tid + i * 128];
            Vs[tid + i * 128] = vsrc[tid + i * 128];
        }
        __syncthreads();

        float s[32];
        #pragma unroll
        for (int k = 0; k < 32; k++) {
            float acc = 0.f;
            #pragma unroll
            for (int d = 0; d < 16; d++) {
                const float4 kv = Ks[k * 16 + d];
                acc += q4[d].x * kv.x + q4[d].y * kv.y +
                       q4[d].z * kv.z + q4[d].w * kv.w;
            }
            s[k] = acc * scale;
        }

        float tm = s[0];
        #pragma unroll
        for (int k = 1; k < 32; k++) tm = fmaxf(tm, s[k]);
        const float mnew = fmaxf(mi, tm);
        const float alpha = exp2f(mi - mnew);
        li *= alpha;
        #pragma unroll
        for (int i = 0; i < 16; i++) {
            o4[i].x *= alpha; o4[i].y *= alpha;
            o4[i].z *= alpha; o4[i].w *= alpha;
        }

        #pragma unroll
        for (int k = 0; k < 32; k++) {
            const float p = exp2f(s[k] - mnew);
            li += p;
            #pragma unroll
            for (int d = 0; d < 16; d++) {
                const float4 vv = Vs[k * 16 + d];
                o4[d].x += p * vv.x; o4[d].y += p * vv.y;
                o4[d].z += p * vv.z; o4[d].w += p * vv.w;
            }
        }
        mi = mnew;
        __syncthreads();
    }

    const float inv = 1.f / li;
    const int b = bh >> 4, h = bh & 15;
    float4* outp = (float4*)(g_att + ((size_t)(b * N_ + q)) * EMB_ + h * HD_);
    #pragma unroll
    for (int d = 0; d < 16; d++)
        outp[d] = make_float4(tf32_rna(o4[d].x * inv), tf32_rna(o4[d].y * inv),
                              tf32_rna(o4[d].z * inv), tf32_rna(o4[d].w * inv));
}

// ---------------------------------------------------------------------------
extern "C" void kernel_launch(void* const* d_in, const int* in_sizes, int n_in,
                              void* d_out, int out_size)
{
    const float* x    = (const float*)d_in[0];
    const float* Wqkv = (const float*)d_in[1];
    const float* bqkv = (const float*)d_in[2];
    const float* Wout = (const float*)d_in[3];
    const float* bout = (const float*)d_in[4];
    float* out = (float*)d_out;

    cudaFuncSetAttribute(tc_gemm_kernel<0>,
                         cudaFuncAttributeMaxDynamicSharedMemorySize, SMEM_BYTES);
    cudaFuncSetAttribute(tc_gemm_kernel<1>,
                         cudaFuncAttributeMaxDynamicSharedMemorySize, SMEM_BYTES);

    float* d_xa;  cudaGetSymbolAddress((void**)&d_xa,  g_xa);
    float* d_w1t; cudaGetSymbolAddress((void**)&d_w1t, g_w1t);
    float* d_w2t; cudaGetSymbolAddress((void**)&d_w2t, g_w2t);

    cvt_tf32_kernel<<<4096, 256>>>(x, d_xa, 1048576);
    transpose_cvt_kernel<<<dim3(96, 32), dim3(32, 8)>>>(Wqkv, d_w1t, 1024, 3072);
    transpose_cvt_kernel<<<dim3(32, 32), dim3(32, 8)>>>(Wout, d_w2t, 1024, 1024);

    tc_gemm_kernel<0><<<dim3(24, 32), 256, SMEM_BYTES>>>(bqkv, nullptr);
    attn_kernel<<<dim3(8, 64), 128>>>();
    tc_gemm_kernel<1><<<dim3(8, 32), 256, SMEM_BYTES>>>(bout, out);
}

// round 4
// speedup vs baseline: 3.7598x; 2.0277x over previous
#include <cuda_runtime.h>
#include <cstdint>

// Problem constants
#define B_    4
#define N_    1024
#define EMB_  1024
#define H_    16
#define HD_   64
#define BQ_   (B_*H_*N_*HD_)   // 4194304 elements per qkv part

// Scratch (static device globals — no allocations allowed)
__device__ float g_xa [4096 * 1024];     // tf32-rounded x
__device__ float g_w1t[3072 * 1024];     // tf32(W_qkv^T)
__device__ float g_w2t[1024 * 1024];     // tf32(W_out^T)
__device__ float g_qkv[3u * BQ_];        // [part][b][h][n][d]; part: 0=K,1=Q,2=V (tf32-rounded)
__device__ float g_att[4096 * 1024];     // attention out, tf32-rounded

// ---------------------------------------------------------------------------
// helpers
// ---------------------------------------------------------------------------
__device__ __forceinline__ float tf32_rna(float x) {
    float r;
    asm("cvt.rna.tf32.f32 %0, %1;" : "=f"(r) : "f"(x));
    return r;
}
__device__ __forceinline__ void cp_async16(uint32_t dst, const void* src) {
    asm volatile("cp.async.cg.shared.global [%0], [%1], 16;\n"
                 :: "r"(dst), "l"(src) : "memory");
}
__device__ __forceinline__ void cp_commit() {
    asm volatile("cp.async.commit_group;\n" ::: "memory");
}
__device__ __forceinline__ void cp_wait0() {
    asm volatile("cp.async.wait_group 0;\n" ::: "memory");
}
__device__ __forceinline__ void cp_wait2() {
    asm volatile("cp.async.wait_group 2;\n" ::: "memory");
}
__device__ __forceinline__ uint32_t smem_u32(const void* p) {
    uint32_t a;
    asm("{ .reg .u64 t; cvta.to.shared.u64 t, %1; cvt.u32.u64 %0, t; }"
        : "=r"(a) : "l"(p));
    return a;
}
// m16n8k8 tf32 mma, acc fp32
__device__ __forceinline__ void mma_tf32(float* c, const uint32_t* a, const uint32_t* b) {
    asm volatile(
        "mma.sync.aligned.m16n8k8.row.col.f32.tf32.tf32.f32 "
        "{%0,%1,%2,%3}, {%4,%5,%6,%7}, {%8,%9}, {%0,%1,%2,%3};"
        : "+f"(c[0]), "+f"(c[1]), "+f"(c[2]), "+f"(c[3])
        : "r"(a[0]), "r"(a[1]), "r"(a[2]), "r"(a[3]),
          "r"(b[0]), "r"(b[1]));
}

// ---------------------------------------------------------------------------
// Prep kernels
// ---------------------------------------------------------------------------
__global__ void cvt_tf32_kernel(const float* __restrict__ in, float* __restrict__ out, int n4) {
    int i = blockIdx.x * blockDim.x + threadIdx.x;
    if (i >= n4) return;
    float4 v = ((const float4*)in)[i];
    v.x = tf32_rna(v.x); v.y = tf32_rna(v.y);
    v.z = tf32_rna(v.z); v.w = tf32_rna(v.w);
    ((float4*)out)[i] = v;
}

__global__ void transpose_cvt_kernel(const float* __restrict__ W, float* __restrict__ Wt,
                                     int Kd, int Nd) {
    __shared__ float ts[32][33];
    int bx = blockIdx.x * 32;   // n base
    int by = blockIdx.y * 32;   // k base
    #pragma unroll
    for (int i = 0; i < 4; i++)
        ts[threadIdx.y + i * 8][threadIdx.x] =
            W[(size_t)(by + threadIdx.y + i * 8) * Nd + bx + threadIdx.x];
    __syncthreads();
    #pragma unroll
    for (int i = 0; i < 4; i++)
        Wt[(size_t)(bx + threadIdx.y + i * 8) * Kd + by + threadIdx.x] =
            tf32_rna(ts[threadIdx.x][threadIdx.y + i * 8]);
}

// ---------------------------------------------------------------------------
// tf32 mma.sync GEMM (as round 3). MODE 0 scatters to g_qkv (tf32-rounded).
// ---------------------------------------------------------------------------
#define KC 32
#define NITER 32
#define ROWSTRIDE 36
#define STAGE_FLOATS (2 * 128 * ROWSTRIDE)
#define SMEM_BYTES (3 * STAGE_FLOATS * 4)

__device__ __forceinline__ void issue_stage(const float* Aptr, const float* Bptr,
                                            uint32_t sbase, int slot, int kiter,
                                            int m0, int n0, int tid) {
    const uint32_t sA = sbase + slot * (STAGE_FLOATS * 4);
    const uint32_t sB = sA + 128 * ROWSTRIDE * 4;
    const int k0 = kiter * KC;
    #pragma unroll
    for (int j = 0; j < 4; j++) {
        int c = tid + j * 256;
        int row = c >> 3, k4 = (c & 7) * 4;
        cp_async16(sA + (row * ROWSTRIDE + k4) * 4,
                   Aptr + (size_t)(m0 + row) * 1024 + k0 + k4);
    }
    #pragma unroll
    for (int j = 0; j < 4; j++) {
        int c = tid + j * 256;
        int row = c >> 3, k4 = (c & 7) * 4;
        cp_async16(sB + (row * ROWSTRIDE + k4) * 4,
                   Bptr + (size_t)(n0 + row) * 1024 + k0 + k4);
    }
}

template<int MODE>
__global__ __launch_bounds__(256, 1) void tc_gemm_kernel(
    const float* __restrict__ bias, float* __restrict__ outParam)
{
    extern __shared__ float smem[];
    const uint32_t sbase = smem_u32(smem);
    const int tid = threadIdx.x;
    const int wid = tid >> 5, lid = tid & 31;
    const int grp = lid >> 2, tig = lid & 3;
    const int warpM = wid >> 2, warpN = wid & 3;
    const int m0 = blockIdx.y * 128, n0 = blockIdx.x * 128;

    const float* Aptr = (MODE == 0) ? g_xa  : g_att;
    const float* Bptr = (MODE == 0) ? g_w1t : g_w2t;

    float acc[4][4][4];
    #pragma unroll
    for (int mf = 0; mf < 4; mf++)
        #pragma unroll
        for (int nf = 0; nf < 4; nf++)
            #pragma unroll
            for (int r = 0; r < 4; r++) acc[mf][nf][r] = 0.f;

    #pragma unroll
    for (int s = 0; s < 3; s++) { issue_stage(Aptr, Bptr, sbase, s, s, m0, n0, tid); cp_commit(); }

    const int arow0 = warpM * 64 + grp;
    const int brow0 = warpN * 32 + grp;

    for (int i = 0; i < NITER; i++) {
        const int slot = i % 3;
        cp_wait2();
        __syncthreads();

        const float* As = smem + slot * STAGE_FLOATS;
        const float* Bs = As + 128 * ROWSTRIDE;

        #pragma unroll
        for (int ks = 0; ks < 4; ks++) {
            const int kc0 = ks * 8 + tig;
            uint32_t a[4][4], b[4][2];
            #pragma unroll
            for (int mf = 0; mf < 4; mf++) {
                const float* ap = As + (arow0 + mf * 16) * ROWSTRIDE + kc0;
                a[mf][0] = __float_as_uint(ap[0]);
                a[mf][1] = __float_as_uint(ap[8 * ROWSTRIDE]);
                a[mf][2] = __float_as_uint(ap[4]);
                a[mf][3] = __float_as_uint(ap[8 * ROWSTRIDE + 4]);
            }
            #pragma unroll
            for (int nf = 0; nf < 4; nf++) {
                const float* bp = Bs + (brow0 + nf * 8) * ROWSTRIDE + kc0;
                b[nf][0] = __float_as_uint(bp[0]);
                b[nf][1] = __float_as_uint(bp[4]);
            }
            #pragma unroll
            for (int mf = 0; mf < 4; mf++)
                #pragma unroll
                for (int nf = 0; nf < 4; nf++)
                    mma_tf32(acc[mf][nf], a[mf], b[nf]);
        }
        __syncthreads();
        if (i + 3 < NITER) issue_stage(Aptr, Bptr, sbase, slot, i + 3, m0, n0, tid);
        cp_commit();
    }

    #pragma unroll
    for (int mf = 0; mf < 4; mf++) {
        const int m = m0 + warpM * 64 + mf * 16 + grp;
        #pragma unroll
        for (int nf = 0; nf < 4; nf++) {
            const int c = n0 + warpN * 32 + nf * 8 + tig * 2;
            const float b0 = bias[c], b1 = bias[c + 1];
            if (MODE == 0) {
                // tf32-round so attention mma inputs are exact tf32
                float2 v0 = make_float2(tf32_rna(acc[mf][nf][0] + b0),
                                        tf32_rna(acc[mf][nf][1] + b1));
                float2 v1 = make_float2(tf32_rna(acc[mf][nf][2] + b0),
                                        tf32_rna(acc[mf][nf][3] + b1));
                const int bb = m >> 10, n = m & 1023;
                const int part = c >> 10, col = c & 1023;
                const int h = col >> 6, d = col & 63;
                float* base = g_qkv + (size_t)part * BQ_ +
                              ((size_t)((bb << 4) + h) * 1024) * 64 + d;
                *(float2*)(base + (size_t)n * 64)       = v0;
                *(float2*)(base + (size_t)(n + 8) * 64) = v1;
            } else {
                float2 v0 = make_float2(acc[mf][nf][0] + b0, acc[mf][nf][1] + b1);
                float2 v1 = make_float2(acc[mf][nf][2] + b0, acc[mf][nf][3] + b1);
                *(float2*)(outParam + (size_t)m * 1024 + c)       = v0;
                *(float2*)(outParam + (size_t)(m + 8) * 1024 + c) = v1;
            }
        }
    }
}

// ---------------------------------------------------------------------------
// Tensor-core flash attention (tf32 mma.sync).
// CTA: 128 queries of one (b,h). 8 warps x 16 query rows. Key tiles of 64.
// SMEM (floats, stride 68 => bank stride 4 mod 32, conflict-free fragments):
//   Q   [128][68]             @ 0      (8704)
//   P   per-warp [16][68]     @ 8704   (8704)
//   K stage s [64][68]        @ 17408 + s*8704
//   Vt stage s [64][68]       @ 17408 + s*8704 + 4352
// ---------------------------------------------------------------------------
#define AT_RS 68
#define AT_QOFF 0
#define AT_POFF 8704
#define AT_SOFF 17408
#define AT_STG  8704
#define AT_VOFF 4352
#define AT_SMEM_BYTES ((17408 + 2 * 8704) * 4)   // 139264

__global__ __launch_bounds__(256, 1) void attn_tc_kernel()
{
    extern __shared__ float smem[];
    const uint32_t sbase = smem_u32(smem);
    const int tid = threadIdx.x;
    const int wid = tid >> 5, lid = tid & 31;
    const int grp = lid >> 2, tig = lid & 3;
    const int bh = blockIdx.y;
    const int q0 = blockIdx.x * 128;

    const float* Kbase = g_qkv + (size_t)0 * BQ_ + (size_t)bh * N_ * HD_;
    const float* Qbase = g_qkv + (size_t)1 * BQ_ + (size_t)bh * N_ * HD_;
    const float* Vbase = g_qkv + (size_t)2 * BQ_ + (size_t)bh * N_ * HD_;

    // ---- preload Q (cp.async) and tile 0 (K cp.async, V ldg) ----
    #pragma unroll
    for (int j = 0; j < 8; j++) {
        int idx = tid + j * 256;              // 0..2047
        int row = idx >> 4, f4 = (idx & 15) * 4;
        cp_async16(sbase + (AT_QOFF + row * AT_RS + f4) * 4,
                   Qbase + (size_t)(q0 + row) * 64 + f4);
    }
    #pragma unroll
    for (int j = 0; j < 4; j++) {
        int idx = tid + j * 256;              // 0..1023
        int row = idx >> 4, f4 = (idx & 15) * 4;
        cp_async16(sbase + (AT_SOFF + row * AT_RS + f4) * 4,
                   Kbase + (size_t)row * 64 + f4);
    }
    cp_commit();

    const int vkey = tid >> 2, vd4 = tid & 3;
    float4 vreg[4];
    #pragma unroll
    for (int i = 0; i < 4; i++)
        vreg[i] = *(const float4*)(Vbase + (size_t)vkey * 64 + (vd4 + i * 4) * 4);

    cp_wait0();
    __syncthreads();
    // transpose-store V tile 0
    #pragma unroll
    for (int i = 0; i < 4; i++) {
        const int p = (vd4 + i * 4) * 4;
        float* vt = smem + AT_SOFF + AT_VOFF;
        vt[(p + 0) * AT_RS + vkey] = tf32_rna(vreg[i].x);
        vt[(p + 1) * AT_RS + vkey] = tf32_rna(vreg[i].y);
        vt[(p + 2) * AT_RS + vkey] = tf32_rna(vreg[i].z);
        vt[(p + 3) * AT_RS + vkey] = tf32_rna(vreg[i].w);
    }

    // Q fragments (per warp, 16 rows x 64 d)
    uint32_t qa[8][4];
    {
        const float* Qs = smem + AT_QOFF + (wid * 16 + grp) * AT_RS;
        #pragma unroll
        for (int ks = 0; ks < 8; ks++) {
            const int kc = ks * 8 + tig;
            qa[ks][0] = __float_as_uint(Qs[kc]);
            qa[ks][1] = __float_as_uint(Qs[8 * AT_RS + kc]);
            qa[ks][2] = __float_as_uint(Qs[kc + 4]);
            qa[ks][3] = __float_as_uint(Qs[8 * AT_RS + kc + 4]);
        }
    }
    __syncthreads();

    float o[8][4];
    #pragma unroll
    for (int nf = 0; nf < 8; nf++)
        #pragma unroll
        for (int r = 0; r < 4; r++) o[nf][r] = 0.f;
    float m0r = -1e30f, m1r = -1e30f, l0 = 0.f, l1 = 0.f;
    const float kl = 0.125f * 1.44269504088896f;   // scale * log2(e)

    float* Pw = smem + AT_POFF + wid * 16 * AT_RS;

    for (int t = 0; t < 16; t++) {
        const int buf = t & 1;
        const float* Ks = smem + AT_SOFF + buf * AT_STG;
        const float* Vt = Ks + AT_VOFF;

        // prefetch tile t+1
        if (t < 15) {
            const uint32_t nb = sbase + (AT_SOFF + (buf ^ 1) * AT_STG) * 4;
            const size_t koff = (size_t)(t + 1) * 64 * 64;
            #pragma unroll
            for (int j = 0; j < 4; j++) {
                int idx = tid + j * 256;
                int row = idx >> 4, f4 = (idx & 15) * 4;
                cp_async16(nb + (row * AT_RS + f4) * 4,
                           Kbase + koff + (size_t)row * 64 + f4);
            }
            cp_commit();
            #pragma unroll
            for (int i = 0; i < 4; i++)
                vreg[i] = *(const float4*)(Vbase + koff + (size_t)vkey * 64 +
                                           (vd4 + i * 4) * 4);
        }

        // ---- QK^T : S = Q (16xK64) * K^T (64 keys) ----
        float s[8][4];
        #pragma unroll
        for (int nf = 0; nf < 8; nf++)
            #pragma unroll
            for (int r = 0; r < 4; r++) s[nf][r] = 0.f;
        #pragma unroll
        for (int ks = 0; ks < 8; ks++) {
            const int kc = ks * 8 + tig;
            #pragma unroll
            for (int nf = 0; nf < 8; nf++) {
                uint32_t b[2];
                const float* kp = Ks + (nf * 8 + grp) * AT_RS + kc;
                b[0] = __float_as_uint(kp[0]);
                b[1] = __float_as_uint(kp[4]);
                mma_tf32(s[nf], qa[ks], b);
            }
        }

        // ---- online softmax ----
        float mx0 = -1e30f, mx1 = -1e30f;
        #pragma unroll
        for (int nf = 0; nf < 8; nf++) {
            mx0 = fmaxf(mx0, fmaxf(s[nf][0], s[nf][1]));
            mx1 = fmaxf(mx1, fmaxf(s[nf][2], s[nf][3]));
        }
        #pragma unroll
        for (int off = 1; off <= 2; off <<= 1) {
            mx0 = fmaxf(mx0, __shfl_xor_sync(0xFFFFFFFFu, mx0, off));
            mx1 = fmaxf(mx1, __shfl_xor_sync(0xFFFFFFFFu, mx1, off));
        }
        const float mn0 = fmaxf(m0r, mx0), mn1 = fmaxf(m1r, mx1);
        const float a0 = exp2f((m0r - mn0) * kl), a1 = exp2f((m1r - mn1) * kl);
        m0r = mn0; m1r = mn1;

        float sum0 = 0.f, sum1 = 0.f;
        #pragma unroll
        for (int nf = 0; nf < 8; nf++) {
            s[nf][0] = exp2f((s[nf][0] - mn0) * kl);
            s[nf][1] = exp2f((s[nf][1] - mn0) * kl);
            s[nf][2] = exp2f((s[nf][2] - mn1) * kl);
            s[nf][3] = exp2f((s[nf][3] - mn1) * kl);
            sum0 += s[nf][0] + s[nf][1];
            sum1 += s[nf][2] + s[nf][3];
        }
        #pragma unroll
        for (int off = 1; off <= 2; off <<= 1) {
            sum0 += __shfl_xor_sync(0xFFFFFFFFu, sum0, off);
            sum1 += __shfl_xor_sync(0xFFFFFFFFu, sum1, off);
        }
        l0 = l0 * a0 + sum0;
        l1 = l1 * a1 + sum1;

        #pragma unroll
        for (int nf = 0; nf < 8; nf++) {
            o[nf][0] *= a0; o[nf][1] *= a0;
            o[nf][2] *= a1; o[nf][3] *= a1;
        }

        // ---- P to per-warp SMEM (tf32-rounded) ----
        #pragma unroll
        for (int nf = 0; nf < 8; nf++) {
            const int c = nf * 8 + 2 * tig;
            *(float2*)(Pw + grp * AT_RS + c) =
                make_float2(tf32_rna(s[nf][0]), tf32_rna(s[nf][1]));
            *(float2*)(Pw + (grp + 8) * AT_RS + c) =
                make_float2(tf32_rna(s[nf][2]), tf32_rna(s[nf][3]));
        }
        __syncwarp();

        // ---- O += P (16x64 keys) * V (64 x d64) ----
        #pragma unroll
        for (int ks = 0; ks < 8; ks++) {
            const int kc = ks * 8 + tig;
            uint32_t a[4];
            a[0] = __float_as_uint(Pw[grp * AT_RS + kc]);
            a[1] = __float_as_uint(Pw[(grp + 8) * AT_RS + kc]);
            a[2] = __float_as_uint(Pw[grp * AT_RS + kc + 4]);
            a[3] = __float_as_uint(Pw[(grp + 8) * AT_RS + kc + 4]);
            #pragma unroll
            for (int nf = 0; nf < 8; nf++) {
                uint32_t b[2];
                const float* vp = Vt + (nf * 8 + grp) * AT_RS + kc;
                b[0] = __float_as_uint(vp[0]);
                b[1] = __float_as_uint(vp[4]);
                mma_tf32(o[nf], a, b);
            }
        }

        __syncthreads();     // all warps done reading buf (K, Vt)
        if (t < 15) {
            cp_wait0();      // K(t+1) landed
            float* vt = smem + AT_SOFF + (buf ^ 1) * AT_STG + AT_VOFF;
            #pragma unroll
            for (int i = 0; i < 4; i++) {
                const int p = (vd4 + i * 4) * 4;
                vt[(p + 0) * AT_RS + vkey] = tf32_rna(vreg[i].x);
                vt[(p + 1) * AT_RS + vkey] = tf32_rna(vreg[i].y);
                vt[(p + 2) * AT_RS + vkey] = tf32_rna(vreg[i].z);
                vt[(p + 3) * AT_RS + vkey] = tf32_rna(vreg[i].w);
            }
            __syncthreads(); // next buf fully visible
        }
    }

    // ---- finalize: O / l, write g_att (tf32-rounded) ----
    const float inv0 = 1.f / l0, inv1 = 1.f / l1;
    const int b = bh >> 4, h = bh & 15;
    const int q_r0 = q0 + wid * 16 + grp;
    float* out0 = g_att + ((size_t)(b * N_ + q_r0)) * EMB_ + h * HD_;
    float* out1 = g_att + ((size_t)(b * N_ + q_r0 + 8)) * EMB_ + h * HD_;
    #pragma unroll
    for (int nf = 0; nf < 8; nf++) {
        const int c = nf * 8 + 2 * tig;
        *(float2*)(out0 + c) = make_float2(tf32_rna(o[nf][0] * inv0),
                                           tf32_rna(o[nf][1] * inv0));
        *(float2*)(out1 + c) = make_float2(tf32_rna(o[nf][2] * inv1),
                                           tf32_rna(o[nf][3] * inv1));
    }
}

// ---------------------------------------------------------------------------
extern "C" void kernel_launch(void* const* d_in, const int* in_sizes, int n_in,
                              void* d_out, int out_size)
{
    const float* x    = (const float*)d_in[0];
    const float* Wqkv = (const float*)d_in[1];
    const float* bqkv = (const float*)d_in[2];
    const float* Wout = (const float*)d_in[3];
    const float* bout = (const float*)d_in[4];
    float* out = (float*)d_out;

    cudaFuncSetAttribute(tc_gemm_kernel<0>,
                         cudaFuncAttributeMaxDynamicSharedMemorySize, SMEM_BYTES);
    cudaFuncSetAttribute(tc_gemm_kernel<1>,
                         cudaFuncAttributeMaxDynamicSharedMemorySize, SMEM_BYTES);
    cudaFuncSetAttribute(attn_tc_kernel,
                         cudaFuncAttributeMaxDynamicSharedMemorySize, AT_SMEM_BYTES);

    float* d_xa;  cudaGetSymbolAddress((void**)&d_xa,  g_xa);
    float* d_w1t; cudaGetSymbolAddress((void**)&d_w1t, g_w1t);
    float* d_w2t; cudaGetSymbolAddress((void**)&d_w2t, g_w2t);

    cvt_tf32_kernel<<<4096, 256>>>(x, d_xa, 1048576);
    transpose_cvt_kernel<<<dim3(96, 32), dim3(32, 8)>>>(Wqkv, d_w1t, 1024, 3072);
    transpose_cvt_kernel<<<dim3(32, 32), dim3(32, 8)>>>(Wout, d_w2t, 1024, 1024);

    tc_gemm_kernel<0><<<dim3(24, 32), 256, SMEM_BYTES>>>(bqkv, nullptr);
    attn_tc_kernel<<<dim3(8, 64), 256, AT_SMEM_BYTES>>>();
    tc_gemm_kernel<1><<<dim3(8, 32), 256, SMEM_BYTES>>>(bout, out);
}

// round 5
// speedup vs baseline: 4.0529x; 1.0780x over previous
#include <cuda_runtime.h>
#include <cstdint>

// Problem constants
#define B_    4
#define N_    1024
#define EMB_  1024
#define H_    16
#define HD_   64
#define BQ_   (B_*H_*N_*HD_)   // 4194304 elements per qkv part

// Scratch (static device globals — no allocations allowed)
__device__ float g_xa [4096 * 1024];     // tf32-rounded x
__device__ float g_w1t[3072 * 1024];     // tf32(W_qkv^T)
__device__ float g_w2t[1024 * 1024];     // tf32(W_out^T)
__device__ float g_qkv[3u * BQ_];        // [part][b][h][n][d]; 0=K,1=Q,2=V (tf32-rounded)
__device__ float g_att[4096 * 1024];     // attention out, tf32-rounded

// ---------------------------------------------------------------------------
// helpers
// ---------------------------------------------------------------------------
__device__ __forceinline__ float tf32_rna(float x) {
    float r;
    asm("cvt.rna.tf32.f32 %0, %1;" : "=f"(r) : "f"(x));
    return r;
}
__device__ __forceinline__ void cp_async16(uint32_t dst, const void* src) {
    asm volatile("cp.async.cg.shared.global [%0], [%1], 16;\n"
                 :: "r"(dst), "l"(src) : "memory");
}
__device__ __forceinline__ void cp_commit() {
    asm volatile("cp.async.commit_group;\n" ::: "memory");
}
__device__ __forceinline__ void cp_wait0() {
    asm volatile("cp.async.wait_group 0;\n" ::: "memory");
}
__device__ __forceinline__ void cp_wait1() {
    asm volatile("cp.async.wait_group 1;\n" ::: "memory");
}
__device__ __forceinline__ uint32_t smem_u32(const void* p) {
    uint32_t a;
    asm("{ .reg .u64 t; cvta.to.shared.u64 t, %1; cvt.u32.u64 %0, t; }"
        : "=r"(a) : "l"(p));
    return a;
}
// m16n8k8 tf32 mma, acc fp32
__device__ __forceinline__ void mma_tf32(float* c, const uint32_t* a, const uint32_t* b) {
    asm volatile(
        "mma.sync.aligned.m16n8k8.row.col.f32.tf32.tf32.f32 "
        "{%0,%1,%2,%3}, {%4,%5,%6,%7}, {%8,%9}, {%0,%1,%2,%3};"
        : "+f"(c[0]), "+f"(c[1]), "+f"(c[2]), "+f"(c[3])
        : "r"(a[0]), "r"(a[1]), "r"(a[2]), "r"(a[3]),
          "r"(b[0]), "r"(b[1]));
}

// ---------------------------------------------------------------------------
// Prep kernels
// ---------------------------------------------------------------------------
__global__ void cvt_tf32_kernel(const float* __restrict__ in, float* __restrict__ out, int n4) {
    int i = blockIdx.x * blockDim.x + threadIdx.x;
    if (i >= n4) return;
    float4 v = ((const float4*)in)[i];
    v.x = tf32_rna(v.x); v.y = tf32_rna(v.y);
    v.z = tf32_rna(v.z); v.w = tf32_rna(v.w);
    ((float4*)out)[i] = v;
}

__global__ void transpose_cvt_kernel(const float* __restrict__ W, float* __restrict__ Wt,
                                     int Kd, int Nd) {
    __shared__ float ts[32][33];
    int bx = blockIdx.x * 32;   // n base
    int by = blockIdx.y * 32;   // k base
    #pragma unroll
    for (int i = 0; i < 4; i++)
        ts[threadIdx.y + i * 8][threadIdx.x] =
            W[(size_t)(by + threadIdx.y + i * 8) * Nd + bx + threadIdx.x];
    __syncthreads();
    #pragma unroll
    for (int i = 0; i < 4; i++)
        Wt[(size_t)(bx + threadIdx.y + i * 8) * Kd + by + threadIdx.x] =
            tf32_rna(ts[threadIdx.x][threadIdx.y + i * 8]);
}

// ---------------------------------------------------------------------------
// tf32 mma.sync GEMM. 128x128 tile, KC=32, 2-stage cp.async, 2 CTAs/SM.
// MODE 0: scatter epilogue -> g_qkv (tf32-rounded, +b_qkv)
// MODE 1: plain epilogue -> outParam (+b_out)
// ---------------------------------------------------------------------------
#define KC 32
#define NITER 32
#define ROWSTRIDE 36
#define STAGE_FLOATS (2 * 128 * ROWSTRIDE)       // 9216 floats / stage
#define SMEM_BYTES (2 * STAGE_FLOATS * 4)        // 73728

__device__ __forceinline__ void issue_stage(const float* Aptr, const float* Bptr,
                                            uint32_t sbase, int slot, int kiter,
                                            int m0, int n0, int tid) {
    const uint32_t sA = sbase + slot * (STAGE_FLOATS * 4);
    const uint32_t sB = sA + 128 * ROWSTRIDE * 4;
    const int k0 = kiter * KC;
    #pragma unroll
    for (int j = 0; j < 4; j++) {
        int c = tid + j * 256;
        int row = c >> 3, k4 = (c & 7) * 4;
        cp_async16(sA + (row * ROWSTRIDE + k4) * 4,
                   Aptr + (size_t)(m0 + row) * 1024 + k0 + k4);
    }
    #pragma unroll
    for (int j = 0; j < 4; j++) {
        int c = tid + j * 256;
        int row = c >> 3, k4 = (c & 7) * 4;
        cp_async16(sB + (row * ROWSTRIDE + k4) * 4,
                   Bptr + (size_t)(n0 + row) * 1024 + k0 + k4);
    }
}

template<int MODE>
__global__ __launch_bounds__(256, 2) void tc_gemm_kernel(
    const float* __restrict__ bias, float* __restrict__ outParam)
{
    extern __shared__ float smem[];
    const uint32_t sbase = smem_u32(smem);
    const int tid = threadIdx.x;
    const int wid = tid >> 5, lid = tid & 31;
    const int grp = lid >> 2, tig = lid & 3;
    const int warpM = wid >> 2, warpN = wid & 3;
    const int m0 = blockIdx.y * 128, n0 = blockIdx.x * 128;

    const float* Aptr = (MODE == 0) ? g_xa  : g_att;
    const float* Bptr = (MODE == 0) ? g_w1t : g_w2t;

    float acc[4][4][4];
    #pragma unroll
    for (int mf = 0; mf < 4; mf++)
        #pragma unroll
        for (int nf = 0; nf < 4; nf++)
            #pragma unroll
            for (int r = 0; r < 4; r++) acc[mf][nf][r] = 0.f;

    issue_stage(Aptr, Bptr, sbase, 0, 0, m0, n0, tid); cp_commit();
    issue_stage(Aptr, Bptr, sbase, 1, 1, m0, n0, tid); cp_commit();

    const int arow0 = warpM * 64 + grp;
    const int brow0 = warpN * 32 + grp;

    for (int i = 0; i < NITER; i++) {
        const int slot = i & 1;
        cp_wait1();
        __syncthreads();

        const float* As = smem + slot * STAGE_FLOATS;
        const float* Bs = As + 128 * ROWSTRIDE;

        #pragma unroll
        for (int ks = 0; ks < 4; ks++) {
            const int kc0 = ks * 8 + tig;
            uint32_t a[4][4], b[4][2];
            #pragma unroll
            for (int mf = 0; mf < 4; mf++) {
                const float* ap = As + (arow0 + mf * 16) * ROWSTRIDE + kc0;
                a[mf][0] = __float_as_uint(ap[0]);
                a[mf][1] = __float_as_uint(ap[8 * ROWSTRIDE]);
                a[mf][2] = __float_as_uint(ap[4]);
                a[mf][3] = __float_as_uint(ap[8 * ROWSTRIDE + 4]);
            }
            #pragma unroll
            for (int nf = 0; nf < 4; nf++) {
                const float* bp = Bs + (brow0 + nf * 8) * ROWSTRIDE + kc0;
                b[nf][0] = __float_as_uint(bp[0]);
                b[nf][1] = __float_as_uint(bp[4]);
            }
            #pragma unroll
            for (int mf = 0; mf < 4; mf++)
                #pragma unroll
                for (int nf = 0; nf < 4; nf++)
                    mma_tf32(acc[mf][nf], a[mf], b[nf]);
        }
        __syncthreads();
        if (i + 2 < NITER) issue_stage(Aptr, Bptr, sbase, slot, i + 2, m0, n0, tid);
        cp_commit();
    }

    #pragma unroll
    for (int mf = 0; mf < 4; mf++) {
        const int m = m0 + warpM * 64 + mf * 16 + grp;
        #pragma unroll
        for (int nf = 0; nf < 4; nf++) {
            const int c = n0 + warpN * 32 + nf * 8 + tig * 2;
            const float b0 = bias[c], b1 = bias[c + 1];
            if (MODE == 0) {
                float2 v0 = make_float2(tf32_rna(acc[mf][nf][0] + b0),
                                        tf32_rna(acc[mf][nf][1] + b1));
                float2 v1 = make_float2(tf32_rna(acc[mf][nf][2] + b0),
                                        tf32_rna(acc[mf][nf][3] + b1));
                const int bb = m >> 10, n = m & 1023;
                const int part = c >> 10, col = c & 1023;
                const int h = col >> 6, d = col & 63;
                float* base = g_qkv + (size_t)part * BQ_ +
                              ((size_t)((bb << 4) + h) * 1024) * 64 + d;
                *(float2*)(base + (size_t)n * 64)       = v0;
                *(float2*)(base + (size_t)(n + 8) * 64) = v1;
            } else {
                float2 v0 = make_float2(acc[mf][nf][0] + b0, acc[mf][nf][1] + b1);
                float2 v1 = make_float2(acc[mf][nf][2] + b0, acc[mf][nf][3] + b1);
                *(float2*)(outParam + (size_t)m * 1024 + c)       = v0;
                *(float2*)(outParam + (size_t)(m + 8) * 1024 + c) = v1;
            }
        }
    }
}

// ---------------------------------------------------------------------------
// Tensor-core flash attention (tf32 mma.sync), 2 CTAs/SM.
// CTA: 128 queries of one (b,h). 8 warps x 16 query rows. Key tiles of 64.
// SMEM (floats, stride 68 => conflict-free fragments):
//   Q/P (aliased)  [128][68]  @ 0        (8704)   Q dead after frag load
//   K stage s [64][68]        @ 8704 + s*8704
//   Vt stage s [64][68]       @ 8704 + s*8704 + 4352
// Total: 3*8704 floats = 104448 B  => 2 CTAs/SM.
// ---------------------------------------------------------------------------
#define AT_RS 68
#define AT_QOFF 0
#define AT_POFF 0
#define AT_SOFF 8704
#define AT_STG  8704
#define AT_VOFF 4352
#define AT_SMEM_BYTES (3 * 8704 * 4)   // 104448

__global__ __launch_bounds__(256, 2) void attn_tc_kernel()
{
    extern __shared__ float smem[];
    const uint32_t sbase = smem_u32(smem);
    const int tid = threadIdx.x;
    const int wid = tid >> 5, lid = tid & 31;
    const int grp = lid >> 2, tig = lid & 3;
    const int bh = blockIdx.y;
    const int q0 = blockIdx.x * 128;

    const float* Kbase = g_qkv + (size_t)0 * BQ_ + (size_t)bh * N_ * HD_;
    const float* Qbase = g_qkv + (size_t)1 * BQ_ + (size_t)bh * N_ * HD_;
    const float* Vbase = g_qkv + (size_t)2 * BQ_ + (size_t)bh * N_ * HD_;

    // ---- preload Q (cp.async) and tile 0 (K cp.async, V ldg) ----
    #pragma unroll
    for (int j = 0; j < 8; j++) {
        int idx = tid + j * 256;              // 0..2047
        int row = idx >> 4, f4 = (idx & 15) * 4;
        cp_async16(sbase + (AT_QOFF + row * AT_RS + f4) * 4,
                   Qbase + (size_t)(q0 + row) * 64 + f4);
    }
    #pragma unroll
    for (int j = 0; j < 4; j++) {
        int idx = tid + j * 256;              // 0..1023
        int row = idx >> 4, f4 = (idx & 15) * 4;
        cp_async16(sbase + (AT_SOFF + row * AT_RS + f4) * 4,
                   Kbase + (size_t)row * 64 + f4);
    }
    cp_commit();

    const int vkey = tid >> 2, vd4 = tid & 3;
    float4 vreg[4];
    #pragma unroll
    for (int i = 0; i < 4; i++)
        vreg[i] = *(const float4*)(Vbase + (size_t)vkey * 64 + (vd4 + i * 4) * 4);

    cp_wait0();
    __syncthreads();
    // transpose-store V tile 0
    #pragma unroll
    for (int i = 0; i < 4; i++) {
        const int p = (vd4 + i * 4) * 4;
        float* vt = smem + AT_SOFF + AT_VOFF;
        vt[(p + 0) * AT_RS + vkey] = tf32_rna(vreg[i].x);
        vt[(p + 1) * AT_RS + vkey] = tf32_rna(vreg[i].y);
        vt[(p + 2) * AT_RS + vkey] = tf32_rna(vreg[i].z);
        vt[(p + 3) * AT_RS + vkey] = tf32_rna(vreg[i].w);
    }

    // Q fragments (per warp, its own 16 rows — same region later used as P)
    uint32_t qa[8][4];
    {
        const float* Qs = smem + AT_QOFF + (wid * 16 + grp) * AT_RS;
        #pragma unroll
        for (int ks = 0; ks < 8; ks++) {
            const int kc = ks * 8 + tig;
            qa[ks][0] = __float_as_uint(Qs[kc]);
            qa[ks][1] = __float_as_uint(Qs[8 * AT_RS + kc]);
            qa[ks][2] = __float_as_uint(Qs[kc + 4]);
            qa[ks][3] = __float_as_uint(Qs[8 * AT_RS + kc + 4]);
        }
    }
    __syncthreads();

    float o[8][4];
    #pragma unroll
    for (int nf = 0; nf < 8; nf++)
        #pragma unroll
        for (int r = 0; r < 4; r++) o[nf][r] = 0.f;
    float m0r = -1e30f, m1r = -1e30f, l0 = 0.f, l1 = 0.f;
    const float kl = 0.125f * 1.44269504088896f;   // scale * log2(e)

    float* Pw = smem + AT_POFF + wid * 16 * AT_RS;

    for (int t = 0; t < 16; t++) {
        const int buf = t & 1;
        const float* Ks = smem + AT_SOFF + buf * AT_STG;
        const float* Vt = Ks + AT_VOFF;

        // prefetch tile t+1
        if (t < 15) {
            const uint32_t nb = sbase + (AT_SOFF + (buf ^ 1) * AT_STG) * 4;
            const size_t koff = (size_t)(t + 1) * 64 * 64;
            #pragma unroll
            for (int j = 0; j < 4; j++) {
                int idx = tid + j * 256;
                int row = idx >> 4, f4 = (idx & 15) * 4;
                cp_async16(nb + (row * AT_RS + f4) * 4,
                           Kbase + koff + (size_t)row * 64 + f4);
            }
            cp_commit();
            #pragma unroll
            for (int i = 0; i < 4; i++)
                vreg[i] = *(const float4*)(Vbase + koff + (size_t)vkey * 64 +
                                           (vd4 + i * 4) * 4);
        }

        // ---- QK^T ----
        float s[8][4];
        #pragma unroll
        for (int nf = 0; nf < 8; nf++)
            #pragma unroll
            for (int r = 0; r < 4; r++) s[nf][r] = 0.f;
        #pragma unroll
        for (int ks = 0; ks < 8; ks++) {
            const int kc = ks * 8 + tig;
            #pragma unroll
            for (int nf = 0; nf < 8; nf++) {
                uint32_t b[2];
                const float* kp = Ks + (nf * 8 + grp) * AT_RS + kc;
                b[0] = __float_as_uint(kp[0]);
                b[1] = __float_as_uint(kp[4]);
                mma_tf32(s[nf], qa[ks], b);
            }
        }

        // ---- online softmax ----
        float mx0 = -1e30f, mx1 = -1e30f;
        #pragma unroll
        for (int nf = 0; nf < 8; nf++) {
            mx0 = fmaxf(mx0, fmaxf(s[nf][0], s[nf][1]));
            mx1 = fmaxf(mx1, fmaxf(s[nf][2], s[nf][3]));
        }
        #pragma unroll
        for (int off = 1; off <= 2; off <<= 1) {
            mx0 = fmaxf(mx0, __shfl_xor_sync(0xFFFFFFFFu, mx0, off));
            mx1 = fmaxf(mx1, __shfl_xor_sync(0xFFFFFFFFu, mx1, off));
        }
        const float mn0 = fmaxf(m0r, mx0), mn1 = fmaxf(m1r, mx1);
        const float a0 = exp2f((m0r - mn0) * kl), a1 = exp2f((m1r - mn1) * kl);
        m0r = mn0; m1r = mn1;

        float sum0 = 0.f, sum1 = 0.f;
        #pragma unroll
        for (int nf = 0; nf < 8; nf++) {
            s[nf][0] = exp2f((s[nf][0] - mn0) * kl);
            s[nf][1] = exp2f((s[nf][1] - mn0) * kl);
            s[nf][2] = exp2f((s[nf][2] - mn1) * kl);
            s[nf][3] = exp2f((s[nf][3] - mn1) * kl);
            sum0 += s[nf][0] + s[nf][1];
            sum1 += s[nf][2] + s[nf][3];
        }
        #pragma unroll
        for (int off = 1; off <= 2; off <<= 1) {
            sum0 += __shfl_xor_sync(0xFFFFFFFFu, sum0, off);
            sum1 += __shfl_xor_sync(0xFFFFFFFFu, sum1, off);
        }
        l0 = l0 * a0 + sum0;
        l1 = l1 * a1 + sum1;

        #pragma unroll
        for (int nf = 0; nf < 8; nf++) {
            o[nf][0] *= a0; o[nf][1] *= a0;
            o[nf][2] *= a1; o[nf][3] *= a1;
        }

        // ---- P to per-warp SMEM (tf32-rounded) ----
        #pragma unroll
        for (int nf = 0; nf < 8; nf++) {
            const int c = nf * 8 + 2 * tig;
            *(float2*)(Pw + grp * AT_RS + c) =
                make_float2(tf32_rna(s[nf][0]), tf32_rna(s[nf][1]));
            *(float2*)(Pw + (grp + 8) * AT_RS + c) =
                make_float2(tf32_rna(s[nf][2]), tf32_rna(s[nf][3]));
        }
        __syncwarp();

        // ---- O += P * V ----
        #pragma unroll
        for (int ks = 0; ks < 8; ks++) {
            const int kc = ks * 8 + tig;
            uint32_t a[4];
            a[0] = __float_as_uint(Pw[grp * AT_RS + kc]);
            a[1] = __float_as_uint(Pw[(grp + 8) * AT_RS + kc]);
            a[2] = __float_as_uint(Pw[grp * AT_RS + kc + 4]);
            a[3] = __float_as_uint(Pw[(grp + 8) * AT_RS + kc + 4]);
            #pragma unroll
            for (int nf = 0; nf < 8; nf++) {
                uint32_t b[2];
                const float* vp = Vt + (nf * 8 + grp) * AT_RS + kc;
                b[0] = __float_as_uint(vp[0]);
                b[1] = __float_as_uint(vp[4]);
                mma_tf32(o[nf], a, b);
            }
        }

        __syncthreads();     // all warps done reading buf (K, Vt)
        if (t < 15) {
            cp_wait0();      // K(t+1) landed
            float* vt = smem + AT_SOFF + (buf ^ 1) * AT_STG + AT_VOFF;
            #pragma unroll
            for (int i = 0; i < 4; i++) {
                const int p = (vd4 + i * 4) * 4;
                vt[(p + 0) * AT_RS + vkey] = tf32_rna(vreg[i].x);
                vt[(p + 1) * AT_RS + vkey] = tf32_rna(vreg[i].y);
                vt[(p + 2) * AT_RS + vkey] = tf32_rna(vreg[i].z);
                vt[(p + 3) * AT_RS + vkey] = tf32_rna(vreg[i].w);
            }
            __syncthreads();
        }
    }

    // ---- finalize ----
    const float inv0 = 1.f / l0, inv1 = 1.f / l1;
    const int b = bh >> 4, h = bh & 15;
    const int q_r0 = q0 + wid * 16 + grp;
    float* out0 = g_att + ((size_t)(b * N_ + q_r0)) * EMB_ + h * HD_;
    float* out1 = g_att + ((size_t)(b * N_ + q_r0 + 8)) * EMB_ + h * HD_;
    #pragma unroll
    for (int nf = 0; nf < 8; nf++) {
        const int c = nf * 8 + 2 * tig;
        *(float2*)(out0 + c) = make_float2(tf32_rna(o[nf][0] * inv0),
                                           tf32_rna(o[nf][1] * inv0));
        *(float2*)(out1 + c) = make_float2(tf32_rna(o[nf][2] * inv1),
                                           tf32_rna(o[nf][3] * inv1));
    }
}

// ---------------------------------------------------------------------------
extern "C" void kernel_launch(void* const* d_in, const int* in_sizes, int n_in,
                              void* d_out, int out_size)
{
    const float* x    = (const float*)d_in[0];
    const float* Wqkv = (const float*)d_in[1];
    const float* bqkv = (const float*)d_in[2];
    const float* Wout = (const float*)d_in[3];
    const float* bout = (const float*)d_in[4];
    float* out = (float*)d_out;

    cudaFuncSetAttribute(tc_gemm_kernel<0>,
                         cudaFuncAttributeMaxDynamicSharedMemorySize, SMEM_BYTES);
    cudaFuncSetAttribute(tc_gemm_kernel<1>,
                         cudaFuncAttributeMaxDynamicSharedMemorySize, SMEM_BYTES);
    cudaFuncSetAttribute(attn_tc_kernel,
                         cudaFuncAttributeMaxDynamicSharedMemorySize, AT_SMEM_BYTES);

    float* d_xa;  cudaGetSymbolAddress((void**)&d_xa,  g_xa);
    float* d_w1t; cudaGetSymbolAddress((void**)&d_w1t, g_w1t);
    float* d_w2t; cudaGetSymbolAddress((void**)&d_w2t, g_w2t);

    cvt_tf32_kernel<<<4096, 256>>>(x, d_xa, 1048576);
    transpose_cvt_kernel<<<dim3(96, 32), dim3(32, 8)>>>(Wqkv, d_w1t, 1024, 3072);
    transpose_cvt_kernel<<<dim3(32, 32), dim3(32, 8)>>>(Wout, d_w2t, 1024, 1024);

    tc_gemm_kernel<0><<<dim3(24, 32), 256, SMEM_BYTES>>>(bqkv, nullptr);
    attn_tc_kernel<<<dim3(8, 64), 256, AT_SMEM_BYTES>>>();
    tc_gemm_kernel<1><<<dim3(8, 32), 256, SMEM_BYTES>>>(bout, out);
}

// round 6
// speedup vs baseline: 8.3589x; 2.0624x over previous
#include <cuda_runtime.h>
#include <cuda_fp16.h>
#include <cstdint>

// Problem constants
#define B_    4
#define N_    1024
#define EMB_  1024
#define H_    16
#define HD_   64
#define BQ_   (B_*H_*N_*HD_)   // 4194304 elements per qkv part

// Scratch (static device globals — no allocations allowed)
__device__ __align__(16) __half g_xa [4096 * 1024];   // fp16(x)
__device__ __align__(16) __half g_w1t[3072 * 1024];   // fp16(W_qkv^T)
__device__ __align__(16) __half g_w2t[1024 * 1024];   // fp16(W_out^T)
__device__ __align__(16) __half g_qkv[3u * BQ_];      // [part][b][h][n][d]; 0=K,1=Q,2=V
__device__ __align__(16) __half g_att[4096 * 1024];   // attention out (B*N, H*hd)

// ---------------------------------------------------------------------------
// helpers
// ---------------------------------------------------------------------------
__device__ __forceinline__ void cp_async16(uint32_t dst, const void* src) {
    asm volatile("cp.async.cg.shared.global [%0], [%1], 16;\n"
                 :: "r"(dst), "l"(src) : "memory");
}
__device__ __forceinline__ void cp_commit() {
    asm volatile("cp.async.commit_group;\n" ::: "memory");
}
__device__ __forceinline__ void cp_wait0() {
    asm volatile("cp.async.wait_group 0;\n" ::: "memory");
}
__device__ __forceinline__ void cp_wait2() {
    asm volatile("cp.async.wait_group 2;\n" ::: "memory");
}
__device__ __forceinline__ uint32_t smem_u32(const void* p) {
    uint32_t a;
    asm("{ .reg .u64 t; cvta.to.shared.u64 t, %1; cvt.u32.u64 %0, t; }"
        : "=r"(a) : "l"(p));
    return a;
}
__device__ __forceinline__ void ldmx4(uint32_t* r, uint32_t addr) {
    asm volatile("ldmatrix.sync.aligned.m8n8.x4.shared.b16 {%0,%1,%2,%3}, [%4];"
                 : "=r"(r[0]), "=r"(r[1]), "=r"(r[2]), "=r"(r[3]) : "r"(addr));
}
__device__ __forceinline__ void ldmx4t(uint32_t* r, uint32_t addr) {
    asm volatile("ldmatrix.sync.aligned.m8n8.x4.trans.shared.b16 {%0,%1,%2,%3}, [%4];"
                 : "=r"(r[0]), "=r"(r[1]), "=r"(r[2]), "=r"(r[3]) : "r"(addr));
}
// m16n8k16 fp16 mma, fp32 acc
__device__ __forceinline__ void mma_f16(float* c, const uint32_t* a,
                                        uint32_t b0, uint32_t b1) {
    asm volatile(
        "mma.sync.aligned.m16n8k16.row.col.f32.f16.f16.f32 "
        "{%0,%1,%2,%3}, {%4,%5,%6,%7}, {%8,%9}, {%0,%1,%2,%3};"
        : "+f"(c[0]), "+f"(c[1]), "+f"(c[2]), "+f"(c[3])
        : "r"(a[0]), "r"(a[1]), "r"(a[2]), "r"(a[3]), "r"(b0), "r"(b1));
}
// XOR swizzle for 64-half (128B) rows: 8 chunks of 8 halves; chunk ^= row&7.
// Conflict-free for 16B cp.async stores, ldmatrix (trans or not), and half2 ops.
__device__ __forceinline__ uint32_t swz64(int row, int col) {
    return (uint32_t)(row * 64 + (((col >> 3) ^ (row & 7)) << 3) + (col & 7));
}

// ---------------------------------------------------------------------------
// Prep kernels: fp16 round (+ transpose for weights)
// ---------------------------------------------------------------------------
__global__ void cvt_half_kernel(const float* __restrict__ in, __half* __restrict__ out, int n4) {
    int i = blockIdx.x * blockDim.x + threadIdx.x;
    if (i >= n4) return;
    float4 v = ((const float4*)in)[i];
    ((__half2*)out)[2 * i]     = __floats2half2_rn(v.x, v.y);
    ((__half2*)out)[2 * i + 1] = __floats2half2_rn(v.z, v.w);
}

// W: (Kd x Nd) row-major fp32 -> Wt: (Nd x Kd) fp16
__global__ void transpose_cvt_kernel(const float* __restrict__ W, __half* __restrict__ Wt,
                                     int Kd, int Nd) {
    __shared__ float ts[32][33];
    int bx = blockIdx.x * 32;   // n base
    int by = blockIdx.y * 32;   // k base
    #pragma unroll
    for (int i = 0; i < 4; i++)
        ts[threadIdx.y + i * 8][threadIdx.x] =
            W[(size_t)(by + threadIdx.y + i * 8) * Nd + bx + threadIdx.x];
    __syncthreads();
    #pragma unroll
    for (int i = 0; i < 4; i++)
        Wt[(size_t)(bx + threadIdx.y + i * 8) * Kd + by + threadIdx.x] =
            __float2half_rn(ts[threadIdx.x][threadIdx.y + i * 8]);
}

// ---------------------------------------------------------------------------
// fp16 mma.sync GEMM: C(Mx Nc) = A(Mx1024) * Bt(Ncx1024)^T (+bias)
// 128x128 tile, 8 warps (2Mx4N, 64x32 each), KC=64, 3-stage cp.async,
// ldmatrix fragments, 2 CTAs/SM.
// MODE 0: scatter epilogue -> g_qkv (fp16) ; MODE 1: plain fp32 -> outParam
// ---------------------------------------------------------------------------
#define KC 64
#define NITER 16
#define STAGE_HALVES (2 * 128 * 64)          // A + B tiles = 16384 halves
#define STAGE_BYTES  (STAGE_HALVES * 2)      // 32768
#define SMEM_BYTES   (3 * STAGE_BYTES)       // 98304

__device__ __forceinline__ void issue_stage(const __half* Aptr, const __half* Bptr,
                                            uint32_t sbase, int slot, int kiter,
                                            int m0, int n0, int tid) {
    const uint32_t sA = sbase + slot * STAGE_BYTES;
    const uint32_t sB = sA + 128 * 64 * 2;
    const int k0 = kiter * KC;
    #pragma unroll
    for (int j = 0; j < 4; j++) {
        int id = tid + j * 256;               // 0..1023
        int row = id >> 3, ch = id & 7;
        cp_async16(sA + swz64(row, ch * 8) * 2,
                   Aptr + (size_t)(m0 + row) * 1024 + k0 + ch * 8);
    }
    #pragma unroll
    for (int j = 0; j < 4; j++) {
        int id = tid + j * 256;
        int row = id >> 3, ch = id & 7;
        cp_async16(sB + swz64(row, ch * 8) * 2,
                   Bptr + (size_t)(n0 + row) * 1024 + k0 + ch * 8);
    }
}

template<int MODE>
__global__ __launch_bounds__(256, 2) void tc_gemm_kernel(
    const float* __restrict__ bias, float* __restrict__ outParam)
{
    extern __shared__ __half smem[];
    const uint32_t sbase = smem_u32(smem);
    const int tid = threadIdx.x;
    const int wid = tid >> 5, lid = tid & 31;
    const int grp = lid >> 2, tig = lid & 3;
    const int warpM = wid >> 2, warpN = wid & 3;
    const int m0 = blockIdx.y * 128, n0 = blockIdx.x * 128;

    const __half* Aptr = (MODE == 0) ? g_xa  : g_att;
    const __half* Bptr = (MODE == 0) ? g_w1t : g_w2t;

    float acc[4][4][4];
    #pragma unroll
    for (int mf = 0; mf < 4; mf++)
        #pragma unroll
        for (int nf = 0; nf < 4; nf++)
            #pragma unroll
            for (int r = 0; r < 4; r++) acc[mf][nf][r] = 0.f;

    #pragma unroll
    for (int s = 0; s < 3; s++) { issue_stage(Aptr, Bptr, sbase, s, s, m0, n0, tid); cp_commit(); }

    // ldmatrix address components (row = t&15, colhi = (t>>4)*8)
    const int lrow = lid & 15;
    const int lcol = (lid >> 4) * 8;

    for (int i = 0; i < NITER; i++) {
        const int slot = i % 3;
        cp_wait2();
        __syncthreads();

        const uint32_t sA = sbase + slot * STAGE_BYTES;
        const uint32_t sB = sA + 128 * 64 * 2;

        #pragma unroll
        for (int ks = 0; ks < 4; ks++) {
            const int kc = ks * 16 + lcol;
            uint32_t a[4][4], b[2][4];
            #pragma unroll
            for (int mf = 0; mf < 4; mf++)
                ldmx4(a[mf], sA + swz64(warpM * 64 + mf * 16 + lrow, kc) * 2);
            #pragma unroll
            for (int nfp = 0; nfp < 2; nfp++)
                ldmx4(b[nfp], sB + swz64(warpN * 32 + nfp * 16 + lrow, kc) * 2);
            #pragma unroll
            for (int mf = 0; mf < 4; mf++)
                #pragma unroll
                for (int nfp = 0; nfp < 2; nfp++) {
                    mma_f16(acc[mf][2 * nfp],     a[mf], b[nfp][0], b[nfp][2]);
                    mma_f16(acc[mf][2 * nfp + 1], a[mf], b[nfp][1], b[nfp][3]);
                }
        }
        __syncthreads();
        if (i + 3 < NITER) issue_stage(Aptr, Bptr, sbase, slot, i + 3, m0, n0, tid);
        cp_commit();
    }

    #pragma unroll
    for (int mf = 0; mf < 4; mf++) {
        const int m = m0 + warpM * 64 + mf * 16 + grp;
        #pragma unroll
        for (int nf = 0; nf < 4; nf++) {
            const int c = n0 + warpN * 32 + nf * 8 + tig * 2;
            const float b0 = bias[c], b1 = bias[c + 1];
            if (MODE == 0) {
                __half2 v0 = __floats2half2_rn(acc[mf][nf][0] + b0, acc[mf][nf][1] + b1);
                __half2 v1 = __floats2half2_rn(acc[mf][nf][2] + b0, acc[mf][nf][3] + b1);
                const int bb = m >> 10, n = m & 1023;
                const int part = c >> 10, col = c & 1023;
                const int h = col >> 6, d = col & 63;
                __half* base = g_qkv + (size_t)part * BQ_ +
                               ((size_t)((bb << 4) + h) * 1024) * 64 + d;
                *(__half2*)(base + (size_t)n * 64)       = v0;
                *(__half2*)(base + (size_t)(n + 8) * 64) = v1;
            } else {
                float2 v0 = make_float2(acc[mf][nf][0] + b0, acc[mf][nf][1] + b1);
                float2 v1 = make_float2(acc[mf][nf][2] + b0, acc[mf][nf][3] + b1);
                *(float2*)(outParam + (size_t)m * 1024 + c)       = v0;
                *(float2*)(outParam + (size_t)(m + 8) * 1024 + c) = v1;
            }
        }
    }
}

// ---------------------------------------------------------------------------
// fp16 tensor-core flash attention. CTA: 128 queries of one (b,h);
// 8 warps x 16 rows; key tiles of 64; double-buffered K/V via cp.async;
// ldmatrix everywhere (V via ldmatrix.trans -- no manual transpose).
// SMEM halves: Q/P aliased [128][64] @0 ; stage s: K [64][64], V [64][64].
// ---------------------------------------------------------------------------
#define AT_KV   (128 * 64)                 // half offset of stage area
#define AT_STG  (2 * 64 * 64)              // halves per stage (K+V)
#define AT_VOF  (64 * 64)                  // V offset within stage
#define AT_SMEM_BYTES ((AT_KV + 2 * AT_STG) * 2)   // 49152

__global__ __launch_bounds__(256, 2) void attn_tc_kernel()
{
    extern __shared__ __half smh[];
    const uint32_t sbase = smem_u32(smh);
    const int tid = threadIdx.x;
    const int wid = tid >> 5, lid = tid & 31;
    const int grp = lid >> 2, tig = lid & 3;
    const int bh = blockIdx.y;
    const int q0 = blockIdx.x * 128;

    const __half* Kbase = g_qkv + (size_t)0 * BQ_ + (size_t)bh * N_ * HD_;
    const __half* Qbase = g_qkv + (size_t)1 * BQ_ + (size_t)bh * N_ * HD_;
    const __half* Vbase = g_qkv + (size_t)2 * BQ_ + (size_t)bh * N_ * HD_;

    // preload Q (128x64) + tile 0 K,V (64x64 each)
    #pragma unroll
    for (int j = 0; j < 4; j++) {
        int id = tid + j * 256;               // 0..1023
        int row = id >> 3, ch = id & 7;
        cp_async16(sbase + swz64(row, ch * 8) * 2,
                   Qbase + (size_t)(q0 + row) * 64 + ch * 8);
    }
    #pragma unroll
    for (int j = 0; j < 2; j++) {
        int id = tid + j * 256;               // 0..511
        int row = id >> 3, ch = id & 7;
        cp_async16(sbase + (AT_KV + swz64(row, ch * 8)) * 2,
                   Kbase + (size_t)row * 64 + ch * 8);
        cp_async16(sbase + (AT_KV + AT_VOF + swz64(row, ch * 8)) * 2,
                   Vbase + (size_t)row * 64 + ch * 8);
    }
    cp_commit();
    cp_wait0();
    __syncthreads();

    const int lrow = lid & 15;
    const int lcol = (lid >> 4) * 8;

    // Q fragments: 4 k-steps x 4 regs (warp's own 16 rows; region reused as P)
    uint32_t qa[4][4];
    #pragma unroll
    for (int ks = 0; ks < 4; ks++)
        ldmx4(qa[ks], sbase + swz64(wid * 16 + lrow, ks * 16 + lcol) * 2);

    float o[8][4];
    #pragma unroll
    for (int nf = 0; nf < 8; nf++)
        #pragma unroll
        for (int r = 0; r < 4; r++) o[nf][r] = 0.f;
    float m0r = -1e30f, m1r = -1e30f, l0 = 0.f, l1 = 0.f;
    const float kl = 0.125f * 1.44269504088896f;   // scale * log2(e)

    // V-trans ldmatrix address components
    const int vrow = ((lid >> 4) & 1) * 8 + (lid & 7);
    const int vcol = ((lid >> 3) & 1) * 8;

    for (int t = 0; t < 16; t++) {
        const int buf = t & 1;
        const uint32_t Ksm = sbase + (AT_KV + buf * AT_STG) * 2;
        const uint32_t Vsm = Ksm + AT_VOF * 2;

        // prefetch tile t+1 into buf^1
        if (t < 15) {
            const uint32_t nK = sbase + (AT_KV + (buf ^ 1) * AT_STG) * 2;
            const size_t koff = (size_t)(t + 1) * 64 * 64;
            #pragma unroll
            for (int j = 0; j < 2; j++) {
                int id = tid + j * 256;
                int row = id >> 3, ch = id & 7;
                cp_async16(nK + swz64(row, ch * 8) * 2,
                           Kbase + koff + (size_t)row * 64 + ch * 8);
                cp_async16(nK + AT_VOF * 2 + swz64(row, ch * 8) * 2,
                           Vbase + koff + (size_t)row * 64 + ch * 8);
            }
            cp_commit();
        }

        // ---- S = Q K^T ----
        float s[8][4];
        #pragma unroll
        for (int nf = 0; nf < 8; nf++)
            #pragma unroll
            for (int r = 0; r < 4; r++) s[nf][r] = 0.f;
        #pragma unroll
        for (int ks = 0; ks < 4; ks++) {
            const int kc = ks * 16 + lcol;
            #pragma unroll
            for (int nfp = 0; nfp < 4; nfp++) {
                uint32_t b[4];
                ldmx4(b, Ksm + swz64(nfp * 16 + lrow, kc) * 2);
                mma_f16(s[2 * nfp],     qa[ks], b[0], b[2]);
                mma_f16(s[2 * nfp + 1], qa[ks], b[1], b[3]);
            }
        }

        // ---- online softmax ----
        float mx0 = -1e30f, mx1 = -1e30f;
        #pragma unroll
        for (int nf = 0; nf < 8; nf++) {
            mx0 = fmaxf(mx0, fmaxf(s[nf][0], s[nf][1]));
            mx1 = fmaxf(mx1, fmaxf(s[nf][2], s[nf][3]));
        }
        #pragma unroll
        for (int off = 1; off <= 2; off <<= 1) {
            mx0 = fmaxf(mx0, __shfl_xor_sync(0xFFFFFFFFu, mx0, off));
            mx1 = fmaxf(mx1, __shfl_xor_sync(0xFFFFFFFFu, mx1, off));
        }
        const float mn0 = fmaxf(m0r, mx0), mn1 = fmaxf(m1r, mx1);
        const float a0 = exp2f((m0r - mn0) * kl), a1 = exp2f((m1r - mn1) * kl);
        m0r = mn0; m1r = mn1;

        float sum0 = 0.f, sum1 = 0.f;
        #pragma unroll
        for (int nf = 0; nf < 8; nf++) {
            s[nf][0] = exp2f((s[nf][0] - mn0) * kl);
            s[nf][1] = exp2f((s[nf][1] - mn0) * kl);
            s[nf][2] = exp2f((s[nf][2] - mn1) * kl);
            s[nf][3] = exp2f((s[nf][3] - mn1) * kl);
            sum0 += s[nf][0] + s[nf][1];
            sum1 += s[nf][2] + s[nf][3];
        }
        #pragma unroll
        for (int off = 1; off <= 2; off <<= 1) {
            sum0 += __shfl_xor_sync(0xFFFFFFFFu, sum0, off);
            sum1 += __shfl_xor_sync(0xFFFFFFFFu, sum1, off);
        }
        l0 = l0 * a0 + sum0;
        l1 = l1 * a1 + sum1;

        #pragma unroll
        for (int nf = 0; nf < 8; nf++) {
            o[nf][0] *= a0; o[nf][1] *= a0;
            o[nf][2] *= a1; o[nf][3] *= a1;
        }

        // ---- P (fp16) into per-warp region (aliases this warp's Q rows) ----
        #pragma unroll
        for (int nf = 0; nf < 8; nf++) {
            const int c = nf * 8 + 2 * tig;
            *(__half2*)(smh + swz64(wid * 16 + grp, c)) =
                __floats2half2_rn(s[nf][0], s[nf][1]);
            *(__half2*)(smh + swz64(wid * 16 + grp + 8, c)) =
                __floats2half2_rn(s[nf][2], s[nf][3]);
        }
        __syncwarp();

        // ---- O += P V  (V fragments via ldmatrix.trans) ----
        #pragma unroll
        for (int ks = 0; ks < 4; ks++) {
            uint32_t a[4];
            ldmx4(a, sbase + swz64(wid * 16 + lrow, ks * 16 + lcol) * 2);
            #pragma unroll
            for (int nfp = 0; nfp < 4; nfp++) {
                uint32_t b[4];
                ldmx4t(b, Vsm + swz64(ks * 16 + vrow, nfp * 16 + vcol) * 2);
                mma_f16(o[2 * nfp],     a, b[0], b[2]);
                mma_f16(o[2 * nfp + 1], a, b[1], b[3]);
            }
        }

        __syncthreads();        // all warps done reading buf
        if (t < 15) {
            cp_wait0();         // tile t+1 landed
            __syncthreads();
        }
    }

    // ---- finalize ----
    const float inv0 = 1.f / l0, inv1 = 1.f / l1;
    const int b = bh >> 4, h = bh & 15;
    const int q_r0 = q0 + wid * 16 + grp;
    __half* out0 = g_att + ((size_t)(b * N_ + q_r0)) * EMB_ + h * HD_;
    __half* out1 = g_att + ((size_t)(b * N_ + q_r0 + 8)) * EMB_ + h * HD_;
    #pragma unroll
    for (int nf = 0; nf < 8; nf++) {
        const int c = nf * 8 + 2 * tig;
        *(__half2*)(out0 + c) = __floats2half2_rn(o[nf][0] * inv0, o[nf][1] * inv0);
        *(__half2*)(out1 + c) = __floats2half2_rn(o[nf][2] * inv1, o[nf][3] * inv1);
    }
}

// ---------------------------------------------------------------------------
extern "C" void kernel_launch(void* const* d_in, const int* in_sizes, int n_in,
                              void* d_out, int out_size)
{
    const float* x    = (const float*)d_in[0];
    const float* Wqkv = (const float*)d_in[1];
    const float* bqkv = (const float*)d_in[2];
    const float* Wout = (const float*)d_in[3];
    const float* bout = (const float*)d_in[4];
    float* out = (float*)d_out;

    cudaFuncSetAttribute(tc_gemm_kernel<0>,
                         cudaFuncAttributeMaxDynamicSharedMemorySize, SMEM_BYTES);
    cudaFuncSetAttribute(tc_gemm_kernel<1>,
                         cudaFuncAttributeMaxDynamicSharedMemorySize, SMEM_BYTES);
    cudaFuncSetAttribute(attn_tc_kernel,
                         cudaFuncAttributeMaxDynamicSharedMemorySize, AT_SMEM_BYTES);

    __half* d_xa;  cudaGetSymbolAddress((void**)&d_xa,  g_xa);
    __half* d_w1t; cudaGetSymbolAddress((void**)&d_w1t, g_w1t);
    __half* d_w2t; cudaGetSymbolAddress((void**)&d_w2t, g_w2t);

    cvt_half_kernel<<<4096, 256>>>(x, d_xa, 1048576);
    transpose_cvt_kernel<<<dim3(96, 32), dim3(32, 8)>>>(Wqkv, d_w1t, 1024, 3072);
    transpose_cvt_kernel<<<dim3(32, 32), dim3(32, 8)>>>(Wout, d_w2t, 1024, 1024);

    tc_gemm_kernel<0><<<dim3(24, 32), 256, SMEM_BYTES>>>(bqkv, nullptr);
    attn_tc_kernel<<<dim3(8, 64), 256, AT_SMEM_BYTES>>>();
    tc_gemm_kernel<1><<<dim3(8, 32), 256, SMEM_BYTES>>>(bout, out);
}

// round 9
// speedup vs baseline: 8.7571x; 1.0476x over previous
#include <cuda_runtime.h>
#include <cuda_fp16.h>
#include <cstdint>

// Problem constants
#define B_    4
#define N_    1024
#define EMB_  1024
#define H_    16
#define HD_   64
#define BQ_   (B_*H_*N_*HD_)   // 4194304 elements per qkv part

// Q pre-scale: (1/sqrt(64)) * log2(e)
#define QSCL  0.18033688011112042f

// Scratch (static device globals — no allocations allowed)
__device__ __align__(16) __half g_xa [4096 * 1024];   // fp16(x)
__device__ __align__(16) __half g_w1t[3072 * 1024];   // fp16(W_qkv^T)
__device__ __align__(16) __half g_w2t[1024 * 1024];   // fp16(W_out^T)
__device__ __align__(16) __half g_qkv[3u * BQ_];      // [part][b][h][n][d]; 0=K,1=Q(pre-scaled),2=V
__device__ __align__(16) __half g_att[4096 * 1024];   // attention out (B*N, H*hd)

// ---------------------------------------------------------------------------
// helpers
// ---------------------------------------------------------------------------
__device__ __forceinline__ void cp_async16(uint32_t dst, const void* src) {
    asm volatile("cp.async.cg.shared.global [%0], [%1], 16;\n"
                 :: "r"(dst), "l"(src) : "memory");
}
__device__ __forceinline__ void cp_commit() {
    asm volatile("cp.async.commit_group;\n" ::: "memory");
}
__device__ __forceinline__ void cp_wait0() {
    asm volatile("cp.async.wait_group 0;\n" ::: "memory");
}
__device__ __forceinline__ void cp_wait1() {
    asm volatile("cp.async.wait_group 1;\n" ::: "memory");
}
__device__ __forceinline__ uint32_t smem_u32(const void* p) {
    uint32_t a;
    asm("{ .reg .u64 t; cvta.to.shared.u64 t, %1; cvt.u32.u64 %0, t; }"
        : "=r"(a) : "l"(p));
    return a;
}
__device__ __forceinline__ void ldmx4(uint32_t* r, uint32_t addr) {
    asm volatile("ldmatrix.sync.aligned.m8n8.x4.shared.b16 {%0,%1,%2,%3}, [%4];"
                 : "=r"(r[0]), "=r"(r[1]), "=r"(r[2]), "=r"(r[3]) : "r"(addr));
}
__device__ __forceinline__ void ldmx4t(uint32_t* r, uint32_t addr) {
    asm volatile("ldmatrix.sync.aligned.m8n8.x4.trans.shared.b16 {%0,%1,%2,%3}, [%4];"
                 : "=r"(r[0]), "=r"(r[1]), "=r"(r[2]), "=r"(r[3]) : "r"(addr));
}
// m16n8k16 fp16 mma, fp32 acc
__device__ __forceinline__ void mma_f16(float* c, const uint32_t* a,
                                        uint32_t b0, uint32_t b1) {
    asm volatile(
        "mma.sync.aligned.m16n8k16.row.col.f32.f16.f16.f32 "
        "{%0,%1,%2,%3}, {%4,%5,%6,%7}, {%8,%9}, {%0,%1,%2,%3};"
        : "+f"(c[0]), "+f"(c[1]), "+f"(c[2]), "+f"(c[3])
        : "r"(a[0]), "r"(a[1]), "r"(a[2]), "r"(a[3]), "r"(b0), "r"(b1));
}
// pack two fp32 -> packed half2 register (cvt.rn.f16x2.f32: d = {hi, lo})
__device__ __forceinline__ uint32_t h2pack(float lo, float hi) {
    uint32_t r;
    asm("cvt.rn.f16x2.f32 %0, %1, %2;" : "=r"(r) : "f"(hi), "f"(lo));
    return r;
}
// XOR swizzle for 64-half (128B) rows: 8 chunks of 8 halves; chunk ^= row&7.
__device__ __forceinline__ uint32_t swz64(int row, int col) {
    return (uint32_t)(row * 64 + (((col >> 3) ^ (row & 7)) << 3) + (col & 7));
}

// ---------------------------------------------------------------------------
// Fused prep kernel: transpose+cvt Wqkv, transpose+cvt Wout, cvt x.
// grid = 3072 (Wqkv tiles) + 1024 (Wout tiles) + 4096 (x chunks), 256 thr.
// ---------------------------------------------------------------------------
__global__ __launch_bounds__(256) void prep_kernel(
    const float* __restrict__ x, const float* __restrict__ Wqkv,
    const float* __restrict__ Wout)
{
    const int bid = blockIdx.x;
    const int tid = threadIdx.x;
    if (bid < 4096) {           // transposes
        __shared__ float ts[32][33];
        const float* W; __half* Wt; int Nd;
        int id;
        if (bid < 3072) { W = Wqkv; Wt = g_w1t; Nd = 3072; id = bid; }
        else            { W = Wout; Wt = g_w2t; Nd = 1024; id = bid - 3072; }
        const int bx = (id % (Nd / 32)) * 32;   // n base
        const int by = (id / (Nd / 32)) * 32;   // k base
        const int tx = tid & 31, ty = tid >> 5;
        #pragma unroll
        for (int i = 0; i < 4; i++)
            ts[ty + i * 8][tx] = W[(size_t)(by + ty + i * 8) * Nd + bx + tx];
        __syncthreads();
        #pragma unroll
        for (int i = 0; i < 4; i++)
            Wt[(size_t)(bx + ty + i * 8) * 1024 + by + tx] =
                __float2half_rn(ts[tx][ty + i * 8]);
    } else {                     // cvt x
        const int i = (bid - 4096) * 256 + tid;
        float4 v = ((const float4*)x)[i];
        ((__half2*)g_xa)[2 * i]     = __floats2half2_rn(v.x, v.y);
        ((__half2*)g_xa)[2 * i + 1] = __floats2half2_rn(v.z, v.w);
    }
}

// ---------------------------------------------------------------------------
// fp16 mma.sync GEMM: C = A(Mx1024) * Bt(Ncx1024)^T (+bias)
// 128x128 tile, 8 warps (2Mx4N), KC=64, 3-stage cp.async, 1 sync/iter.
// MODE 0: scatter epilogue -> g_qkv (fp16, Q part pre-scaled)
// MODE 1: plain fp32 epilogue -> outParam
// ---------------------------------------------------------------------------
#define KC 64
#define NITER 16
#define STAGE_BYTES  (2 * 128 * 64 * 2)      // 32768
#define SMEM_BYTES   (3 * STAGE_BYTES)       // 98304

__device__ __forceinline__ void issue_stage(const __half* Aptr, const __half* Bptr,
                                            uint32_t sbase, int slot, int kiter,
                                            int m0, int n0, int tid) {
    const uint32_t sA = sbase + slot * STAGE_BYTES;
    const uint32_t sB = sA + 128 * 64 * 2;
    const int k0 = kiter * KC;
    #pragma unroll
    for (int j = 0; j < 4; j++) {
        int id = tid + j * 256;
        int row = id >> 3, ch = id & 7;
        cp_async16(sA + swz64(row, ch * 8) * 2,
                   Aptr + (size_t)(m0 + row) * 1024 + k0 + ch * 8);
    }
    #pragma unroll
    for (int j = 0; j < 4; j++) {
        int id = tid + j * 256;
        int row = id >> 3, ch = id & 7;
        cp_async16(sB + swz64(row, ch * 8) * 2,
                   Bptr + (size_t)(n0 + row) * 1024 + k0 + ch * 8);
    }
}

template<int MODE>
__global__ __launch_bounds__(256, 2) void tc_gemm_kernel(
    const float* __restrict__ bias, float* __restrict__ outParam)
{
    extern __shared__ __half smem[];
    const uint32_t sbase = smem_u32(smem);
    const int tid = threadIdx.x;
    const int wid = tid >> 5, lid = tid & 31;
    const int grp = lid >> 2, tig = lid & 3;
    const int warpM = wid >> 2, warpN = wid & 3;
    const int m0 = blockIdx.y * 128, n0 = blockIdx.x * 128;

    const __half* Aptr = (MODE == 0) ? g_xa  : g_att;
    const __half* Bptr = (MODE == 0) ? g_w1t : g_w2t;

    float acc[4][4][4];
    #pragma unroll
    for (int mf = 0; mf < 4; mf++)
        #pragma unroll
        for (int nf = 0; nf < 4; nf++)
            #pragma unroll
            for (int r = 0; r < 4; r++) acc[mf][nf][r] = 0.f;

    issue_stage(Aptr, Bptr, sbase, 0, 0, m0, n0, tid); cp_commit();
    issue_stage(Aptr, Bptr, sbase, 1, 1, m0, n0, tid); cp_commit();
    cp_wait1();                 // stage 0 done
    __syncthreads();

    const int lrow = lid & 15;
    const int lcol = (lid >> 4) * 8;

    for (int i = 0; i < NITER; i++) {
        const int slot = i % 3;
        // prefetch stage i+2 into slot (i+2)%3 (freed at iter i-1; bottom sync protects)
        if (i + 2 < NITER)
            issue_stage(Aptr, Bptr, sbase, (i + 2) % 3, i + 2, m0, n0, tid);
        cp_commit();

        const uint32_t sA = sbase + slot * STAGE_BYTES;
        const uint32_t sB = sA + 128 * 64 * 2;

        #pragma unroll
        for (int ks = 0; ks < 4; ks++) {
            const int kc = ks * 16 + lcol;
            uint32_t a[4][4], b[2][4];
            #pragma unroll
            for (int mf = 0; mf < 4; mf++)
                ldmx4(a[mf], sA + swz64(warpM * 64 + mf * 16 + lrow, kc) * 2);
            #pragma unroll
            for (int nfp = 0; nfp < 2; nfp++)
                ldmx4(b[nfp], sB + swz64(warpN * 32 + nfp * 16 + lrow, kc) * 2);
            #pragma unroll
            for (int mf = 0; mf < 4; mf++)
                #pragma unroll
                for (int nfp = 0; nfp < 2; nfp++) {
                    mma_f16(acc[mf][2 * nfp],     a[mf], b[nfp][0], b[nfp][2]);
                    mma_f16(acc[mf][2 * nfp + 1], a[mf], b[nfp][1], b[nfp][3]);
                }
        }
        cp_wait1();             // stage i+1 complete
        __syncthreads();        // visible + all warps done with stage i
    }

    const float qs = (MODE == 0 && (n0 >> 10) == 1) ? QSCL : 1.0f;
    #pragma unroll
    for (int mf = 0; mf < 4; mf++) {
        const int m = m0 + warpM * 64 + mf * 16 + grp;
        #pragma unroll
        for (int nf = 0; nf < 4; nf++) {
            const int c = n0 + warpN * 32 + nf * 8 + tig * 2;
            const float b0 = bias[c], b1 = bias[c + 1];
            if (MODE == 0) {
                __half2 v0 = __floats2half2_rn((acc[mf][nf][0] + b0) * qs,
                                               (acc[mf][nf][1] + b1) * qs);
                __half2 v1 = __floats2half2_rn((acc[mf][nf][2] + b0) * qs,
                                               (acc[mf][nf][3] + b1) * qs);
                const int bb = m >> 10, n = m & 1023;
                const int part = c >> 10, col = c & 1023;
                const int h = col >> 6, d = col & 63;
                __half* base = g_qkv + (size_t)part * BQ_ +
                               ((size_t)((bb << 4) + h) * 1024) * 64 + d;
                *(__half2*)(base + (size_t)n * 64)       = v0;
                *(__half2*)(base + (size_t)(n + 8) * 64) = v1;
            } else {
                float2 v0 = make_float2(acc[mf][nf][0] + b0, acc[mf][nf][1] + b1);
                float2 v1 = make_float2(acc[mf][nf][2] + b0, acc[mf][nf][3] + b1);
                *(float2*)(outParam + (size_t)m * 1024 + c)       = v0;
                *(float2*)(outParam + (size_t)(m + 8) * 1024 + c) = v1;
            }
        }
    }
}

// ---------------------------------------------------------------------------
// fp16 tensor-core flash attention. CTA: 128 queries of one (b,h);
// 8 warps x 16 rows; key tiles of 64; double-buffered K/V cp.async;
// P fed to PV directly from S fragments (no smem round-trip); 1 sync/tile.
// SMEM halves: Q [128][64] @0 ; stage s: K [64][64], V [64][64].
// ---------------------------------------------------------------------------
#define AT_KV   (128 * 64)
#define AT_STG  (2 * 64 * 64)
#define AT_VOF  (64 * 64)
#define AT_SMEM_BYTES ((AT_KV + 2 * AT_STG) * 2)   // 49152

__global__ __launch_bounds__(256, 2) void attn_tc_kernel()
{
    extern __shared__ __half smh[];
    const uint32_t sbase = smem_u32(smh);
    const int tid = threadIdx.x;
    const int wid = tid >> 5, lid = tid & 31;
    const int grp = lid >> 2, tig = lid & 3;
    const int bh = blockIdx.y;
    const int q0 = blockIdx.x * 128;

    const __half* Kbase = g_qkv + (size_t)0 * BQ_ + (size_t)bh * N_ * HD_;
    const __half* Qbase = g_qkv + (size_t)1 * BQ_ + (size_t)bh * N_ * HD_;
    const __half* Vbase = g_qkv + (size_t)2 * BQ_ + (size_t)bh * N_ * HD_;

    // preload Q (128x64) + tile 0 K,V
    #pragma unroll
    for (int j = 0; j < 4; j++) {
        int id = tid + j * 256;
        int row = id >> 3, ch = id & 7;
        cp_async16(sbase + swz64(row, ch * 8) * 2,
                   Qbase + (size_t)(q0 + row) * 64 + ch * 8);
    }
    #pragma unroll
    for (int j = 0; j < 2; j++) {
        int id = tid + j * 256;
        int row = id >> 3, ch = id & 7;
        cp_async16(sbase + (AT_KV + swz64(row, ch * 8)) * 2,
                   Kbase + (size_t)row * 64 + ch * 8);
        cp_async16(sbase + (AT_KV + AT_VOF + swz64(row, ch * 8)) * 2,
                   Vbase + (size_t)row * 64 + ch * 8);
    }
    cp_commit();
    cp_wait0();
    __syncthreads();

    const int lrow = lid & 15;
    const int lcol = (lid >> 4) * 8;

    uint32_t qa[4][4];
    #pragma unroll
    for (int ks = 0; ks < 4; ks++)
        ldmx4(qa[ks], sbase + swz64(wid * 16 + lrow, ks * 16 + lcol) * 2);

    float o[8][4];
    #pragma unroll
    for (int nf = 0; nf < 8; nf++)
        #pragma unroll
        for (int r = 0; r < 4; r++) o[nf][r] = 0.f;
    float m0r = -1e30f, m1r = -1e30f, l0 = 0.f, l1 = 0.f;

    const int vrow = ((lid >> 4) & 1) * 8 + (lid & 7);
    const int vcol = ((lid >> 3) & 1) * 8;

    for (int t = 0; t < 16; t++) {
        const int buf = t & 1;
        const uint32_t Ksm = sbase + (AT_KV + buf * AT_STG) * 2;
        const uint32_t Vsm = Ksm + AT_VOF * 2;

        // prefetch tile t+1 into buf^1 (freed; previous bottom sync protects)
        if (t < 15) {
            const uint32_t nK = sbase + (AT_KV + (buf ^ 1) * AT_STG) * 2;
            const size_t koff = (size_t)(t + 1) * 64 * 64;
            #pragma unroll
            for (int j = 0; j < 2; j++) {
                int id = tid + j * 256;
                int row = id >> 3, ch = id & 7;
                cp_async16(nK + swz64(row, ch * 8) * 2,
                           Kbase + koff + (size_t)row * 64 + ch * 8);
                cp_async16(nK + AT_VOF * 2 + swz64(row, ch * 8) * 2,
                           Vbase + koff + (size_t)row * 64 + ch * 8);
            }
            cp_commit();
        }

        // ---- S = Qs K^T (log2 domain; Q pre-scaled) ----
        float s[8][4];
        #pragma unroll
        for (int nf = 0; nf < 8; nf++)
            #pragma unroll
            for (int r = 0; r < 4; r++) s[nf][r] = 0.f;
        #pragma unroll
        for (int ks = 0; ks < 4; ks++) {
            const int kc = ks * 16 + lcol;
            #pragma unroll
            for (int nfp = 0; nfp < 4; nfp++) {
                uint32_t b[4];
                ldmx4(b, Ksm + swz64(nfp * 16 + lrow, kc) * 2);
                mma_f16(s[2 * nfp],     qa[ks], b[0], b[2]);
                mma_f16(s[2 * nfp + 1], qa[ks], b[1], b[3]);
            }
        }

        // ---- online softmax (log2 domain) ----
        float mx0 = -1e30f, mx1 = -1e30f;
        #pragma unroll
        for (int nf = 0; nf < 8; nf++) {
            mx0 = fmaxf(mx0, fmaxf(s[nf][0], s[nf][1]));
            mx1 = fmaxf(mx1, fmaxf(s[nf][2], s[nf][3]));
        }
        #pragma unroll
        for (int off = 1; off <= 2; off <<= 1) {
            mx0 = fmaxf(mx0, __shfl_xor_sync(0xFFFFFFFFu, mx0, off));
            mx1 = fmaxf(mx1, __shfl_xor_sync(0xFFFFFFFFu, mx1, off));
        }
        const float mn0 = fmaxf(m0r, mx0), mn1 = fmaxf(m1r, mx1);
        const float a0 = exp2f(m0r - mn0), a1 = exp2f(m1r - mn1);
        m0r = mn0; m1r = mn1;

        float sum0 = 0.f, sum1 = 0.f;
        #pragma unroll
        for (int nf = 0; nf < 8; nf++) {
            s[nf][0] = exp2f(s[nf][0] - mn0);
            s[nf][1] = exp2f(s[nf][1] - mn0);
            s[nf][2] = exp2f(s[nf][2] - mn1);
            s[nf][3] = exp2f(s[nf][3] - mn1);
            sum0 += s[nf][0] + s[nf][1];
            sum1 += s[nf][2] + s[nf][3];
        }
        #pragma unroll
        for (int off = 1; off <= 2; off <<= 1) {
            sum0 += __shfl_xor_sync(0xFFFFFFFFu, sum0, off);
            sum1 += __shfl_xor_sync(0xFFFFFFFFu, sum1, off);
        }
        l0 = l0 * a0 + sum0;
        l1 = l1 * a1 + sum1;

        #pragma unroll
        for (int nf = 0; nf < 8; nf++) {
            o[nf][0] *= a0; o[nf][1] *= a0;
            o[nf][2] *= a1; o[nf][3] *= a1;
        }

        // ---- O += P V : P directly from S fragments (C->A layout identity) ----
        #pragma unroll
        for (int ks = 0; ks < 4; ks++) {
            uint32_t a[4];
            a[0] = h2pack(s[2 * ks][0],     s[2 * ks][1]);
            a[1] = h2pack(s[2 * ks][2],     s[2 * ks][3]);
            a[2] = h2pack(s[2 * ks + 1][0], s[2 * ks + 1][1]);
            a[3] = h2pack(s[2 * ks + 1][2], s[2 * ks + 1][3]);
            #pragma unroll
            for (int nfp = 0; nfp < 4; nfp++) {
                uint32_t b[4];
                ldmx4t(b, Vsm + swz64(ks * 16 + vrow, nfp * 16 + vcol) * 2);
                mma_f16(o[2 * nfp],     a, b[0], b[2]);
                mma_f16(o[2 * nfp + 1], a, b[1], b[3]);
            }
        }

        if (t < 15) {
            cp_wait0();          // tile t+1 landed
            __syncthreads();     // visible to all; all warps done with buf
        }
    }

    // ---- finalize ----
    const float inv0 = 1.f / l0, inv1 = 1.f / l1;
    const int b = bh >> 4, h = bh & 15;
    const int q_r0 = q0 + wid * 16 + grp;
    __half* out0 = g_att + ((size_t)(b * N_ + q_r0)) * EMB_ + h * HD_;
    __half* out1 = g_att + ((size_t)(b * N_ + q_r0 + 8)) * EMB_ + h * HD_;
    #pragma unroll
    for (int nf = 0; nf < 8; nf++) {
        const int c = nf * 8 + 2 * tig;
        *(__half2*)(out0 + c) = __floats2half2_rn(o[nf][0] * inv0, o[nf][1] * inv0);
        *(__half2*)(out1 + c) = __floats2half2_rn(o[nf][2] * inv1, o[nf][3] * inv1);
    }
}

// ---------------------------------------------------------------------------
extern "C" void kernel_launch(void* const* d_in, const int* in_sizes, int n_in,
                              void* d_out, int out_size)
{
    const float* x    = (const float*)d_in[0];
    const float* Wqkv = (const float*)d_in[1];
    const float* bqkv = (const float*)d_in[2];
    const float* Wout = (const float*)d_in[3];
    const float* bout = (const float*)d_in[4];
    float* out = (float*)d_out;

    cudaFuncSetAttribute(tc_gemm_kernel<0>,
                         cudaFuncAttributeMaxDynamicSharedMemorySize, SMEM_BYTES);
    cudaFuncSetAttribute(tc_gemm_kernel<1>,
                         cudaFuncAttributeMaxDynamicSharedMemorySize, SMEM_BYTES);
    cudaFuncSetAttribute(attn_tc_kernel,
                         cudaFuncAttributeMaxDynamicSharedMemorySize, AT_SMEM_BYTES);

    prep_kernel<<<8192, 256>>>(x, Wqkv, Wout);
    tc_gemm_kernel<0><<<dim3(24, 32), 256, SMEM_BYTES>>>(bqkv, nullptr);
    attn_tc_kernel<<<dim3(8, 64), 256, AT_SMEM_BYTES>>>();
    tc_gemm_kernel<1><<<dim3(8, 32), 256, SMEM_BYTES>>>(bout, out);
}